// round 1
// baseline (speedup 1.0000x reference)
#include <cuda_runtime.h>
#include <cuda_bf16.h>
#include <math.h>

// ---------------- problem constants ----------------
#define N0 4096
#define N1 2048
#define N2 1024
#define N3 512
#define NE 65536
#define FH 64      // hidden
#define FO 128     // out
#define MAXD 256   // max neighbors per row (avg ~17, Poisson(16) max << 256)

// ---------------- static device scratch (no allocation allowed) ----------------
__device__ float g_A0[(size_t)N0*N0];
__device__ float g_A1[(size_t)N1*N1];
__device__ float g_A2[(size_t)N2*N2];
__device__ float g_A3[(size_t)N3*N3];
__device__ float g_Rg[(size_t)N1*N0];
__device__ float g_Cg[(size_t)N0*N1];
__device__ float g_Y[(size_t)N0*FO];
__device__ float g_Z[(size_t)N0*FO];
__device__ float g_S[(size_t)N0*FO];
__device__ float g_x0[N0*FH], g_x1[N1*FH], g_x2[N2*FH], g_x3[N3*FH];
__device__ float g_hbuf[N0*FH];
__device__ float g_up[N1*FH];
__device__ float g_H[N0*FO];
__device__ float g_U[N0*FO];
__device__ float g_res[N0*FO];
__device__ float g_feat1[(size_t)N0*512];
__device__ float g_gout[(size_t)N0*512];
__device__ float g_feat2[N0*FO];
__device__ float g_dinv0[N0], g_dfix0[N0];
__device__ float g_dinv1[N1], g_dfix1[N1];
__device__ float g_dinv2[N2], g_dfix2[N2];
__device__ float g_dinv3[N3], g_dfix3[N3];
__device__ float g_score[N0];
__device__ int   g_perm1[N1]; __device__ float g_vals1[N1];
__device__ int   g_perm2[N2]; __device__ float g_vals2[N2];
__device__ int   g_perm3[N3]; __device__ float g_vals3[N3];
__device__ int   g_nbr[(size_t)N0*MAXD];
__device__ int   g_cnt[N0];
__device__ float g_es[N0*4], g_ed[N0*4];

// ---------------- generic SGEMM (row-major A[MxK] @ B[KxN] -> C[MxN]) ----------------
template<int BM,int BN,int BK,int TM,int TN>
__global__ void __launch_bounds__((BM/TM)*(BN/TN))
sgemm_k(int M,int N,int K,const float* __restrict__ A,const float* __restrict__ B,float* __restrict__ C){
    constexpr int THREADS=(BM/TM)*(BN/TN);
    __shared__ float As[BK][BM+1];
    __shared__ float Bs[BK][BN];
    const int bm = blockIdx.y*BM, bn = blockIdx.x*BN;
    const int tid = threadIdx.x;
    const int tcol = tid % (BN/TN);
    const int trow = tid / (BN/TN);
    float acc[TM][TN];
    #pragma unroll
    for(int i=0;i<TM;i++)
        #pragma unroll
        for(int j=0;j<TN;j++) acc[i][j]=0.f;

    for(int k0=0;k0<K;k0+=BK){
        #pragma unroll 4
        for(int i=tid;i<BM*BK;i+=THREADS){
            int m=i/BK, k=i%BK;
            int gm=bm+m, gk=k0+k;
            float v=0.f;
            if(gm<M && gk<K) v=A[(size_t)gm*K+gk];
            As[k][m]=v;
        }
        #pragma unroll 4
        for(int i=tid;i<BK*BN;i+=THREADS){
            int k=i/BN, n=i%BN;
            int gk=k0+k, gn=bn+n;
            float v=0.f;
            if(gk<K && gn<N) v=B[(size_t)gk*N+gn];
            Bs[k][n]=v;
        }
        __syncthreads();
        #pragma unroll
        for(int kk=0;kk<BK;kk++){
            float ra[TM], rb[TN];
            #pragma unroll
            for(int i=0;i<TM;i++) ra[i]=As[kk][trow*TM+i];
            #pragma unroll
            for(int j=0;j<TN;j++) rb[j]=Bs[kk][tcol*TN+j];
            #pragma unroll
            for(int i=0;i<TM;i++)
                #pragma unroll
                for(int j=0;j<TN;j++) acc[i][j]+=ra[i]*rb[j];
        }
        __syncthreads();
    }
    #pragma unroll
    for(int i=0;i<TM;i++){
        int gm=bm+trow*TM+i;
        if(gm>=M) continue;
        #pragma unroll
        for(int j=0;j<TN;j++){
            int gn=bn+tcol*TN+j;
            if(gn<N) C[(size_t)gm*N+gn]=acc[i][j];
        }
    }
}

// ---------------- small kernels ----------------
__global__ void k_buildA0(const int* __restrict__ ei, float* __restrict__ A){
    int e = blockIdx.x*blockDim.x+threadIdx.x;
    if(e<NE){
        int s=ei[e];
        int d=ei[NE+e];
        atomicAdd(&A[(size_t)d*N0+s], 1.0f);
    }
}

// warp per row: diag + rowsum -> dinv, dfix
__global__ void k_degree(const float* __restrict__ A,int n,float* __restrict__ dinv,float* __restrict__ dfix){
    int w = (blockIdx.x*blockDim.x+threadIdx.x)>>5;
    int lane = threadIdx.x&31;
    if(w>=n) return;
    const float* row = A+(size_t)w*n;
    float s=0.f;
    for(int j=lane;j<n;j+=32) s+=row[j];
    #pragma unroll
    for(int o=16;o;o>>=1) s+=__shfl_xor_sync(0xffffffffu,s,o);
    if(lane==0){
        float d = row[w];
        float fx = (d==0.f)?2.f:0.f;
        dinv[w]=rsqrtf(s+fx);
        dfix[w]=fx;
    }
}

__global__ void k_scale(const float* __restrict__ Y,const float* __restrict__ dinv,int tot,int f,float* __restrict__ Z){
    int t=blockIdx.x*blockDim.x+threadIdx.x;
    if(t<tot) Z[t]=Y[t]*dinv[t/f];
}

__global__ void k_gcnep(const float* __restrict__ S,const float* __restrict__ Z,
                        const float* __restrict__ dinv,const float* __restrict__ dfix,
                        const float* __restrict__ b,float* __restrict__ out,int tot,int f,int dorelu){
    int t=blockIdx.x*blockDim.x+threadIdx.x;
    if(t>=tot) return;
    int i=t/f;
    float v = dinv[i]*(S[t]+dfix[i]*Z[t]) + b[t%f];
    out[t] = dorelu ? fmaxf(v,0.f) : v;
}

// warp per row: score = tanh(dot(x_i, p)/||p||)   (f=64)
__global__ void k_score(const float* __restrict__ x,const float* __restrict__ p,int n,float* __restrict__ sc){
    int w=(blockIdx.x*blockDim.x+threadIdx.x)>>5;
    int lane=threadIdx.x&31;
    if(w>=n) return;
    float d=0.f, pn=0.f;
    for(int c=lane;c<FH;c+=32){ float pv=p[c]; d+=x[(size_t)w*FH+c]*pv; pn+=pv*pv; }
    #pragma unroll
    for(int o=16;o;o>>=1){ d+=__shfl_xor_sync(0xffffffffu,d,o); pn+=__shfl_xor_sync(0xffffffffu,pn,o); }
    if(lane==0) sc[w]=tanhf(d*rsqrtf(pn));
}

// bitonic sort descending (ties: index asc), n pow2 <= 4096
__global__ void __launch_bounds__(1024) k_sort(const float* __restrict__ score,int n,int k,int* __restrict__ perm,float* __restrict__ vals){
    __shared__ float kk[4096];
    __shared__ int   ii[4096];
    int t=threadIdx.x;
    for(int i=t;i<n;i+=1024){ kk[i]=score[i]; ii[i]=i; }
    __syncthreads();
    for(int size=2;size<=n;size<<=1){
        for(int stride=size>>1;stride>0;stride>>=1){
            for(int i=t;i<(n>>1);i+=1024){
                int lo = 2*i - (i&(stride-1));
                int hi = lo+stride;
                bool up = ((lo & size)==0);
                float ka=kk[lo], kb=kk[hi];
                int ia=ii[lo], ib=ii[hi];
                bool beforeBA = (kb>ka) || (kb==ka && ib<ia); // hi should precede lo (desc order)
                bool sw = up ? beforeBA : !beforeBA;
                if(sw){ kk[lo]=kb;kk[hi]=ka;ii[lo]=ib;ii[hi]=ia; }
            }
            __syncthreads();
        }
    }
    for(int i=t;i<k;i+=1024){ perm[i]=ii[i]; vals[i]=kk[i]; }
}

// R[i,k] = A[perm_i, k] + (k==perm_i)
__global__ void k_gatherR(const float* __restrict__ A,int n,const int* __restrict__ perm,int m,float* __restrict__ R){
    size_t t=(size_t)blockIdx.x*blockDim.x+threadIdx.x;
    if(t>=(size_t)m*n) return;
    int i=(int)(t/n), k=(int)(t%n);
    int pi=perm[i];
    R[t]=A[(size_t)pi*n+k] + ((k==pi)?1.f:0.f);
}
// C[k,j] = A[k, perm_j] + (k==perm_j)
__global__ void k_gatherC(const float* __restrict__ A,int n,const int* __restrict__ perm,int m,float* __restrict__ C){
    size_t t=(size_t)blockIdx.x*blockDim.x+threadIdx.x;
    if(t>=(size_t)m*n) return;
    int k=(int)(t/m), j=(int)(t%m);
    int pj=perm[j];
    C[t]=A[(size_t)k*n+pj] + ((k==pj)?1.f:0.f);
}
__global__ void k_diag0(float* __restrict__ A,int m){
    int i=blockIdx.x*blockDim.x+threadIdx.x;
    if(i<m) A[(size_t)i*m+i]=0.f;
}
// h[i,:] = x[perm_i,:]*vals_i   (f=64)
__global__ void k_poolgather(const float* __restrict__ x,const int* __restrict__ perm,const float* __restrict__ vals,int tot,float* __restrict__ h){
    int t=blockIdx.x*blockDim.x+threadIdx.x;
    if(t>=tot) return;
    int i=t/FH, c=t%FH;
    h[t]=x[(size_t)perm[i]*FH+c]*vals[i];
}
// h[perm_i,:] += xs[i,:]
__global__ void k_scatadd(float* __restrict__ h,const int* __restrict__ perm,const float* __restrict__ xs,int tot,int f){
    int t=blockIdx.x*blockDim.x+threadIdx.x;
    if(t>=tot) return;
    int i=t/f, c=t%f;
    h[(size_t)perm[i]*f+c]+=xs[t];
}
// layernorm, block of 128 per row, F=128
__global__ void k_ln(const float* __restrict__ h,const float* __restrict__ g,const float* __restrict__ b,float* __restrict__ u){
    __shared__ float red[128];
    int i=blockIdx.x, t=threadIdx.x;
    float v=h[(size_t)i*FO+t];
    red[t]=v; __syncthreads();
    for(int o=64;o;o>>=1){ if(t<o) red[t]+=red[t+o]; __syncthreads(); }
    float mu=red[0]/FO; __syncthreads();
    float d=v-mu;
    red[t]=d*d; __syncthreads();
    for(int o=64;o;o>>=1){ if(t<o) red[t]+=red[t+o]; __syncthreads(); }
    float var=red[0]/FO;
    u[(size_t)i*FO+t]=d*rsqrtf(var+1e-6f)*g[t]+b[t];
}
// warp per row: ordered compaction of mask row (A0>0 || self)
__global__ void k_buildcsr(const float* __restrict__ A){
    int w=(blockIdx.x*blockDim.x+threadIdx.x)>>5;
    int lane=threadIdx.x&31;
    if(w>=N0) return;
    const float* row=A+(size_t)w*N0;
    int cnt=0;
    for(int base=0;base<N0;base+=32){
        int s=base+lane;
        bool pred=(row[s]>0.f)||(s==w);
        unsigned m=__ballot_sync(0xffffffffu,pred);
        if(pred){
            int off=cnt+__popc(m&((1u<<lane)-1u));
            if(off<MAXD) g_nbr[(size_t)w*MAXD+off]=s;
        }
        cnt+=__popc(m);
    }
    if(lane==0) g_cnt[w]=min(cnt,MAXD);
}
// warp per node: es/ed = <feat[n,h,:], a[h,:]>
__global__ void k_esed(const float* __restrict__ feat,const float* __restrict__ asrc,const float* __restrict__ adst,int heads,float* __restrict__ es,float* __restrict__ ed){
    int w=(blockIdx.x*blockDim.x+threadIdx.x)>>5;
    int lane=threadIdx.x&31;
    if(w>=N0) return;
    for(int h=0;h<heads;h++){
        float a=0.f,d=0.f;
        for(int c=lane;c<FO;c+=32){
            float f=feat[(size_t)w*(heads*FO)+h*FO+c];
            a+=f*asrc[h*FO+c];
            d+=f*adst[h*FO+c];
        }
        #pragma unroll
        for(int o=16;o;o>>=1){ a+=__shfl_xor_sync(0xffffffffu,a,o); d+=__shfl_xor_sync(0xffffffffu,d,o); }
        if(lane==0){ es[w*heads+h]=a; ed[w*heads+h]=d; }
    }
}
// one block per dst; sparse masked softmax over neighbors + aggregation
template<int HEADS>
__global__ void __launch_bounds__(128) k_gat(const float* __restrict__ feat,const float* __restrict__ es,const float* __restrict__ ed,float* __restrict__ out){
    __shared__ int snbr[MAXD];
    __shared__ float salpha[MAXD*HEADS];
    __shared__ float smax[HEADS], sinv[HEADS];
    int d=blockIdx.x, t=threadIdx.x;
    int cnt=g_cnt[d];
    for(int i=t;i<cnt;i+=128) snbr[i]=g_nbr[(size_t)d*MAXD+i];
    __syncthreads();
    for(int i=t;i<cnt;i+=128){
        int s=snbr[i];
        #pragma unroll
        for(int h=0;h<HEADS;h++){
            float l=ed[d*HEADS+h]+es[s*HEADS+h];
            l = (l>0.f)? l : 0.2f*l;
            salpha[i*HEADS+h]=l;
        }
    }
    __syncthreads();
    if(t<HEADS){
        float mx=-1e30f;
        for(int i=0;i<cnt;i++) mx=fmaxf(mx,salpha[i*HEADS+t]);
        float sm=0.f;
        for(int i=0;i<cnt;i++) sm+=expf(salpha[i*HEADS+t]-mx);
        smax[t]=mx; sinv[t]=1.f/sm;
    }
    __syncthreads();
    for(int i=t;i<cnt*HEADS;i+=128){
        int h=i%HEADS;
        salpha[i]=expf(salpha[i]-smax[h])*sinv[h];
    }
    __syncthreads();
    #pragma unroll
    for(int h=0;h<HEADS;h++){
        float acc=0.f;
        for(int i=0;i<cnt;i++)
            acc += salpha[i*HEADS+h]*feat[(size_t)snbr[i]*(HEADS*FO)+h*FO+t];
        out[(size_t)d*(HEADS*FO)+h*FO+t]=acc;
    }
}
__global__ void k_bias_elu(float* __restrict__ io,const float* __restrict__ b,int tot,int f){
    int t=blockIdx.x*blockDim.x+threadIdx.x;
    if(t>=tot) return;
    float v=io[t]+b[t%f];
    io[t]= (v>0.f)? v : expm1f(v);
}
__global__ void k_final(const float* __restrict__ g2,const float* __restrict__ g2b,
                        const float* __restrict__ res,const float* __restrict__ resb,
                        float* __restrict__ out,int tot,int f){
    int t=blockIdx.x*blockDim.x+threadIdx.x;
    if(t>=tot) return;
    out[t]=g2[t]+g2b[t%f]+res[t]+resb[t%f];
}

// ---------------- host orchestration ----------------
static inline int cdiv(int a,int b){return (a+b-1)/b;}

static void gemm(int M,int N,int K,const float*A,const float*B,float*C){
    if(N<=64 && M>=1024){
        dim3 g(cdiv(N,64),cdiv(M,32));
        sgemm_k<32,64,16,2,8><<<g,128>>>(M,N,K,A,B,C);
    } else {
        long b128=(long)cdiv(M,128)*cdiv(N,128);
        if(b128>=120){
            dim3 g(cdiv(N,128),cdiv(M,128));
            sgemm_k<128,128,16,8,8><<<g,256>>>(M,N,K,A,B,C);
        } else {
            dim3 g(cdiv(N,64),cdiv(M,64));
            sgemm_k<64,64,16,4,4><<<g,256>>>(M,N,K,A,B,C);
        }
    }
}

template<typename T> static T* symaddr(const void* sym){
    void* p=nullptr;
    cudaGetSymbolAddress(&p, sym);
    return (T*)p;
}

extern "C" void kernel_launch(void* const* d_in, const int* in_sizes, int n_in,
                              void* d_out, int out_size) {
    // inputs
    const float* x      =(const float*)d_in[0];
    const int*   ei     =(const int*  )d_in[1];
    const float* w0=(const float*)d_in[2],  *b0=(const float*)d_in[3];
    const float* w1=(const float*)d_in[4],  *b1=(const float*)d_in[5];
    const float* w2=(const float*)d_in[6],  *b2=(const float*)d_in[7];
    const float* w3=(const float*)d_in[8],  *b3=(const float*)d_in[9];
    const float* p1=(const float*)d_in[10], *p2=(const float*)d_in[11], *p3=(const float*)d_in[12];
    const float* uw0=(const float*)d_in[13],*ub0=(const float*)d_in[14];
    const float* uw1=(const float*)d_in[15],*ub1=(const float*)d_in[16];
    const float* uw2=(const float*)d_in[17],*ub2=(const float*)d_in[18];
    const float* lng=(const float*)d_in[19],*lnb=(const float*)d_in[20];
    const float* resw=(const float*)d_in[21],*resb=(const float*)d_in[22];
    const float* g1w=(const float*)d_in[23],*g1as=(const float*)d_in[24],*g1ad=(const float*)d_in[25],*g1b=(const float*)d_in[26];
    const float* g2w=(const float*)d_in[27],*g2as=(const float*)d_in[28],*g2ad=(const float*)d_in[29],*g2b=(const float*)d_in[30];

    // scratch symbol addresses
    float* A0=symaddr<float>(g_A0); float* A1=symaddr<float>(g_A1);
    float* A2=symaddr<float>(g_A2); float* A3=symaddr<float>(g_A3);
    float* Rg=symaddr<float>(g_Rg); float* Cg=symaddr<float>(g_Cg);
    float* Y=symaddr<float>(g_Y);   float* Z=symaddr<float>(g_Z);   float* S=symaddr<float>(g_S);
    float* x0b=symaddr<float>(g_x0);float* x1b=symaddr<float>(g_x1);
    float* x2b=symaddr<float>(g_x2);float* x3b=symaddr<float>(g_x3);
    float* hb=symaddr<float>(g_hbuf); float* upb=symaddr<float>(g_up);
    float* Hb=symaddr<float>(g_H);  float* Ub=symaddr<float>(g_U);  float* Rb=symaddr<float>(g_res);
    float* F1=symaddr<float>(g_feat1); float* GO=symaddr<float>(g_gout); float* F2=symaddr<float>(g_feat2);
    float* di0=symaddr<float>(g_dinv0); float* df0=symaddr<float>(g_dfix0);
    float* di1=symaddr<float>(g_dinv1); float* df1=symaddr<float>(g_dfix1);
    float* di2=symaddr<float>(g_dinv2); float* df2=symaddr<float>(g_dfix2);
    float* di3=symaddr<float>(g_dinv3); float* df3=symaddr<float>(g_dfix3);
    float* sc=symaddr<float>(g_score);
    int* pm1=symaddr<int>(g_perm1); float* vl1=symaddr<float>(g_vals1);
    int* pm2=symaddr<int>(g_perm2); float* vl2=symaddr<float>(g_vals2);
    int* pm3=symaddr<int>(g_perm3); float* vl3=symaddr<float>(g_vals3);
    float* ES=symaddr<float>(g_es); float* ED=symaddr<float>(g_ed);
    float* out=(float*)d_out;

    auto gcn=[&](int n,const float* A,const float* hin,int kin,const float* W,int kout,const float* b,
                 float* dinv,float* dfix,float* xout,bool relu,bool deg){
        if(deg) k_degree<<<cdiv(n,8),256>>>(A,n,dinv,dfix);
        gemm(n,kout,kin,hin,W,Y);
        int tot=n*kout;
        k_scale<<<cdiv(tot,256),256>>>(Y,dinv,tot,kout,Z);
        gemm(n,kout,n,A,Z,S);
        k_gcnep<<<cdiv(tot,256),256>>>(S,Z,dinv,dfix,b,xout,tot,kout,relu?1:0);
    };
    auto pool=[&](int nf,const float* Af,const float* xin,const float* p,int kk,
                  int* perm,float* vals,float* Aout,float* hout){
        k_score<<<cdiv(nf,8),256>>>(xin,p,nf,sc);
        k_sort<<<1,1024>>>(sc,nf,kk,perm,vals);
        size_t tot=(size_t)kk*nf;
        k_gatherR<<<(int)cdiv((int)tot,256),256>>>(Af,nf,perm,kk,Rg);
        k_gatherC<<<(int)cdiv((int)tot,256),256>>>(Af,nf,perm,kk,Cg);
        gemm(kk,kk,nf,Rg,Cg,Aout);
        k_diag0<<<cdiv(kk,256),256>>>(Aout,kk);
        k_poolgather<<<cdiv(kk*FH,256),256>>>(xin,perm,vals,kk*FH,hout);
    };

    // ---- build A0 ----
    cudaMemsetAsync(A0,0,(size_t)N0*N0*sizeof(float),0);
    k_buildA0<<<cdiv(NE,256),256>>>(ei,A0);

    // ---- down path ----
    gcn(N0,A0,x,3, w0,FH,b0, di0,df0, x0b, true,true);
    pool(N0,A0,x0b,p1,N1,pm1,vl1,A1,hb);
    gcn(N1,A1,hb,FH, w1,FH,b1, di1,df1, x1b, true,true);
    pool(N1,A1,x1b,p2,N2,pm2,vl2,A2,hb);
    gcn(N2,A2,hb,FH, w2,FH,b2, di2,df2, x2b, true,true);
    pool(N2,A2,x2b,p3,N3,pm3,vl3,A3,hb);
    gcn(N3,A3,hb,FH, w3,FH,b3, di3,df3, x3b, true,true);

    // ---- up path ----
    cudaMemcpyAsync(hb,x2b,(size_t)N2*FH*sizeof(float),cudaMemcpyDeviceToDevice,0);
    k_scatadd<<<cdiv(N3*FH,256),256>>>(hb,pm3,x3b,N3*FH,FH);
    gcn(N2,A2,hb,FH, uw0,FH,ub0, di2,df2, upb, true,false);

    cudaMemcpyAsync(hb,x1b,(size_t)N1*FH*sizeof(float),cudaMemcpyDeviceToDevice,0);
    k_scatadd<<<cdiv(N2*FH,256),256>>>(hb,pm2,upb,N2*FH,FH);
    gcn(N1,A1,hb,FH, uw1,FH,ub1, di1,df1, upb, true,false);

    cudaMemcpyAsync(hb,x0b,(size_t)N0*FH*sizeof(float),cudaMemcpyDeviceToDevice,0);
    k_scatadd<<<cdiv(N1*FH,256),256>>>(hb,pm1,upb,N1*FH,FH);
    gcn(N0,A0,hb,FH, uw2,FO,ub2, di0,df0, Hb, false,false);

    // ---- layernorm + residual ----
    k_ln<<<N0,128>>>(Hb,lng,lnb,Ub);
    gemm(N0,FO,FO,Ub,resw,Rb);

    // ---- GAT layers (sparse via CSR of A0 mask) ----
    k_buildcsr<<<cdiv(N0,8),256>>>(A0);

    gemm(N0,4*FO,FO,Ub,g1w,F1);
    k_esed<<<cdiv(N0,8),256>>>(F1,g1as,g1ad,4,ES,ED);
    k_gat<4><<<N0,128>>>(F1,ES,ED,GO);
    k_bias_elu<<<cdiv(N0*4*FO,256),256>>>(GO,g1b,N0*4*FO,4*FO);

    gemm(N0,FO,4*FO,GO,g2w,F2);
    k_esed<<<cdiv(N0,8),256>>>(F2,g2as,g2ad,1,ES,ED);
    k_gat<1><<<N0,128>>>(F2,ES,ED,S);

    k_final<<<cdiv(N0*FO,256),256>>>(S,g2b,Rb,resb,out,N0*FO,FO);
}

// round 2
// speedup vs baseline: 1.4459x; 1.4459x over previous
#include <cuda_runtime.h>
#include <cuda_bf16.h>
#include <math.h>

// ---------------- problem constants ----------------
#define N0 4096
#define N1 2048
#define N2 1024
#define N3 512
#define NE 65536
#define FH 64      // hidden
#define FO 128     // out
#define MAXD0 128  // max nnz per row of A0 (+forced diag); deg ~ Poisson(16)
#define MAXD1 2048 // = NCOL at level1 (cannot overflow)
#define MAXD2 1024
#define MAXD3 512

// ---------------- static device scratch ----------------
__device__ float g_A0[(size_t)N0*N0];
__device__ int   g_idx0[(size_t)N0*MAXD0]; __device__ float g_val0[(size_t)N0*MAXD0]; __device__ int g_cnt0[N0];
__device__ int   g_idx1[(size_t)N1*MAXD1]; __device__ float g_val1[(size_t)N1*MAXD1]; __device__ int g_cnt1[N1];
__device__ int   g_idx2[(size_t)N2*MAXD2]; __device__ float g_val2[(size_t)N2*MAXD2]; __device__ int g_cnt2[N2];
__device__ int   g_idx3[(size_t)N3*MAXD3]; __device__ float g_val3[(size_t)N3*MAXD3]; __device__ int g_cnt3[N3];
__device__ float g_Y[(size_t)N0*FO];
__device__ float g_Z[(size_t)N0*FO];
__device__ float g_S[(size_t)N0*FO];
__device__ float g_x0[N0*FH], g_x1[N1*FH], g_x2[N2*FH], g_x3[N3*FH];
__device__ float g_hbuf[N0*FH];
__device__ float g_up[N1*FH];
__device__ float g_H[N0*FO];
__device__ float g_U[N0*FO];
__device__ float g_res[N0*FO];
__device__ float g_feat1[(size_t)N0*512];
__device__ float g_gout[(size_t)N0*512];
__device__ float g_dinv0[N0], g_dfix0[N0];
__device__ float g_dinv1[N1], g_dinv2[N2], g_dinv3[N3];
__device__ float g_score[N0];
__device__ int   g_perm1[N1]; __device__ float g_vals1[N1];
__device__ int   g_perm2[N2]; __device__ float g_vals2[N2];
__device__ int   g_perm3[N3]; __device__ float g_vals3[N3];
__device__ int   g_ipos[N0];
__device__ float g_es[N0*4], g_ed[N0*4];

// ---------------- generic SGEMM (row-major A[MxK] @ B[KxN] -> C[MxN]) ----------------
template<int BM,int BN,int BK,int TM,int TN>
__global__ void __launch_bounds__((BM/TM)*(BN/TN))
sgemm_k(int M,int N,int K,const float* __restrict__ A,const float* __restrict__ B,float* __restrict__ C){
    constexpr int THREADS=(BM/TM)*(BN/TN);
    __shared__ float As[BK][BM+1];
    __shared__ float Bs[BK][BN];
    const int bm = blockIdx.y*BM, bn = blockIdx.x*BN;
    const int tid = threadIdx.x;
    const int tcol = tid % (BN/TN);
    const int trow = tid / (BN/TN);
    float acc[TM][TN];
    #pragma unroll
    for(int i=0;i<TM;i++)
        #pragma unroll
        for(int j=0;j<TN;j++) acc[i][j]=0.f;

    for(int k0=0;k0<K;k0+=BK){
        #pragma unroll 4
        for(int i=tid;i<BM*BK;i+=THREADS){
            int m=i/BK, k=i%BK;
            int gm=bm+m, gk=k0+k;
            float v=0.f;
            if(gm<M && gk<K) v=A[(size_t)gm*K+gk];
            As[k][m]=v;
        }
        #pragma unroll 4
        for(int i=tid;i<BK*BN;i+=THREADS){
            int k=i/BN, n=i%BN;
            int gk=k0+k, gn=bn+n;
            float v=0.f;
            if(gk<K && gn<N) v=B[(size_t)gk*N+gn];
            Bs[k][n]=v;
        }
        __syncthreads();
        #pragma unroll
        for(int kk=0;kk<BK;kk++){
            float ra[TM], rb[TN];
            #pragma unroll
            for(int i=0;i<TM;i++) ra[i]=As[kk][trow*TM+i];
            #pragma unroll
            for(int j=0;j<TN;j++) rb[j]=Bs[kk][tcol*TN+j];
            #pragma unroll
            for(int i=0;i<TM;i++)
                #pragma unroll
                for(int j=0;j<TN;j++) acc[i][j]+=ra[i]*rb[j];
        }
        __syncthreads();
    }
    #pragma unroll
    for(int i=0;i<TM;i++){
        int gm=bm+trow*TM+i;
        if(gm>=M) continue;
        #pragma unroll
        for(int j=0;j<TN;j++){
            int gn=bn+tcol*TN+j;
            if(gn<N) C[(size_t)gm*N+gn]=acc[i][j];
        }
    }
}

// ---------------- graph build ----------------
__global__ void k_buildA0(const int* __restrict__ ei, float* __restrict__ A){
    int e = blockIdx.x*blockDim.x+threadIdx.x;
    if(e<NE){
        int s=ei[e];
        int d=ei[NE+e];
        atomicAdd(&A[(size_t)d*N0+s], 1.0f);
    }
}

// warp per row: compact (A0[row,s]!=0 || s==row), store raw vals, compute dinv/dfix
__global__ void k_csr0(const float* __restrict__ A,int* __restrict__ idx,float* __restrict__ val,
                       int* __restrict__ cnt,float* __restrict__ dinv,float* __restrict__ dfix){
    int w=(blockIdx.x*blockDim.x+threadIdx.x)>>5;
    int lane=threadIdx.x&31;
    if(w>=N0) return;
    const float* row=A+(size_t)w*N0;
    int c=0; float rs=0.f;
    for(int base=0;base<N0;base+=32){
        int s=base+lane;
        float v=row[s];
        bool p=(v!=0.f)||(s==w);
        unsigned m=__ballot_sync(0xffffffffu,p);
        if(p){
            int off=c+__popc(m&((1u<<lane)-1u));
            idx[(size_t)w*MAXD0+off]=s;
            val[(size_t)w*MAXD0+off]=v;
            rs+=v;
        }
        c+=__popc(m);
    }
    #pragma unroll
    for(int o=16;o;o>>=1) rs+=__shfl_xor_sync(0xffffffffu,rs,o);
    if(lane==0){
        float d=row[w];
        float fx=(d==0.f)?2.f:0.f;
        cnt[w]=c;
        dfix[w]=fx;
        dinv[w]=rsqrtf(rs+fx);
    }
}

// ---------------- GCN pieces ----------------
__global__ void k_scale(const float* __restrict__ Y,const float* __restrict__ dinv,int tot,int f,float* __restrict__ Z){
    int t=blockIdx.x*blockDim.x+threadIdx.x;
    if(t<tot) Z[t]=Y[t]*dinv[t/f];
}

// CSR SpMM fused with GCN epilogue. blockDim=256, each group of F threads does one row.
template<int F>
__global__ void k_spmm(int n,const int* __restrict__ idx,const float* __restrict__ val,
                       const int* __restrict__ cnt,int maxd,
                       const float* __restrict__ Z,const float* __restrict__ dinv,
                       const float* __restrict__ dfix,const float* __restrict__ b,
                       float* __restrict__ out,int relu){
    int r = blockIdx.x*(256/F) + threadIdx.x/F;
    int c = threadIdx.x%F;
    if(r>=n) return;
    int cn=cnt[r];
    const int* ip=idx+(size_t)r*maxd;
    const float* vp=val+(size_t)r*maxd;
    float acc=0.f;
    for(int e=0;e<cn;e++)
        acc += vp[e]*Z[(size_t)ip[e]*F+c];
    float fx = dfix? dfix[r] : 2.0f;
    float v = dinv[r]*(acc + fx*Z[(size_t)r*F+c]) + b[c];
    out[(size_t)r*F+c] = relu? fmaxf(v,0.f) : v;
}

// ---------------- pooling ----------------
__global__ void k_score(const float* __restrict__ x,const float* __restrict__ p,int n,float* __restrict__ sc){
    int w=(blockIdx.x*blockDim.x+threadIdx.x)>>5;
    int lane=threadIdx.x&31;
    if(w>=n) return;
    float d=0.f, pn=0.f;
    for(int c=lane;c<FH;c+=32){ float pv=p[c]; d+=x[(size_t)w*FH+c]*pv; pn+=pv*pv; }
    #pragma unroll
    for(int o=16;o;o>>=1){ d+=__shfl_xor_sync(0xffffffffu,d,o); pn+=__shfl_xor_sync(0xffffffffu,pn,o); }
    if(lane==0) sc[w]=tanhf(d*rsqrtf(pn));
}

__global__ void __launch_bounds__(1024) k_sort(const float* __restrict__ score,int n,int k,int* __restrict__ perm,float* __restrict__ vals){
    __shared__ float kk[4096];
    __shared__ int   ii[4096];
    int t=threadIdx.x;
    for(int i=t;i<n;i+=1024){ kk[i]=score[i]; ii[i]=i; }
    __syncthreads();
    for(int size=2;size<=n;size<<=1){
        for(int stride=size>>1;stride>0;stride>>=1){
            for(int i=t;i<(n>>1);i+=1024){
                int lo = 2*i - (i&(stride-1));
                int hi = lo+stride;
                bool up = ((lo & size)==0);
                float ka=kk[lo], kb=kk[hi];
                int ia=ii[lo], ib=ii[hi];
                bool beforeBA = (kb>ka) || (kb==ka && ib<ia);
                bool sw = up ? beforeBA : !beforeBA;
                if(sw){ kk[lo]=kb;kk[hi]=ka;ii[lo]=ib;ii[hi]=ia; }
            }
            __syncthreads();
        }
    }
    for(int i=t;i<k;i+=1024){ perm[i]=ii[i]; vals[i]=kk[i]; }
}

__global__ void k_iposset(const int* __restrict__ perm,int m,int* __restrict__ ipos){
    int i=blockIdx.x*blockDim.x+threadIdx.x;
    if(i<m) ipos[perm[i]]=i;
}

// SpGEMM: out[i,:] = ((Ain+I)[perm_i,:] @ (Ain+I)[:,perm])  restricted, diag zeroed.
// Input CSR may or may not contain its diagonal entry (HASDIAG).
template<int NCOL,bool HASDIAG>
__global__ void __launch_bounds__(256) k_spgemm(
        const int* __restrict__ inIdx,const float* __restrict__ inVal,const int* __restrict__ inCnt,int inMaxd,
        const int* __restrict__ perm,const int* __restrict__ ipos,
        int* __restrict__ outIdx,float* __restrict__ outVal,int* __restrict__ outCnt,int outMaxd,
        float* __restrict__ dinv){
    __shared__ float acc[NCOL];
    int i=blockIdx.x, t=threadIdx.x;
    for(int j=t;j<NCOL;j+=256) acc[j]=0.f;
    __syncthreads();
    int r0=perm[i];
    int cr=inCnt[r0];
    int total = cr + (HASDIAG?0:1);
    const int* rip=inIdx+(size_t)r0*inMaxd;
    const float* rvp=inVal+(size_t)r0*inMaxd;
    int warp=t>>5, lane=t&31;
    for(int e=warp;e<total;e+=8){
        int k; float rv;
        if(e<cr){ k=rip[e]; rv=rvp[e] + ((HASDIAG && k==r0)?1.f:0.f); }
        else    { k=r0; rv=1.f; }
        int ck=inCnt[k];
        const int* kip=inIdx+(size_t)k*inMaxd;
        const float* kvp=inVal+(size_t)k*inMaxd;
        int tot2 = ck + (HASDIAG?0:1);
        for(int f=lane;f<tot2;f+=32){
            int s; float cv;
            if(f<ck){ s=kip[f]; cv=kvp[f] + ((HASDIAG && s==k)?1.f:0.f); }
            else    { s=k; cv=1.f; }
            int j=ipos[s];
            if(j>=0) atomicAdd(&acc[j], rv*cv);
        }
    }
    __syncthreads();
    if(t==0) acc[i]=0.f;   // remove self loops
    __syncthreads();
    if(warp==0){
        int c=0; float rs=0.f;
        for(int base=0;base<NCOL;base+=32){
            int j=base+lane;
            float v=acc[j];
            bool p=(v!=0.f);
            unsigned m=__ballot_sync(0xffffffffu,p);
            if(p){
                int off=c+__popc(m&((1u<<lane)-1u));
                outIdx[(size_t)i*outMaxd+off]=j;
                outVal[(size_t)i*outMaxd+off]=v;
                rs+=v;
            }
            c+=__popc(m);
        }
        #pragma unroll
        for(int o=16;o;o>>=1) rs+=__shfl_xor_sync(0xffffffffu,rs,o);
        if(lane==0){ outCnt[i]=c; dinv[i]=rsqrtf(rs+2.f); }
    }
}

__global__ void k_poolgather(const float* __restrict__ x,const int* __restrict__ perm,const float* __restrict__ vals,int tot,float* __restrict__ h){
    int t=blockIdx.x*blockDim.x+threadIdx.x;
    if(t>=tot) return;
    int i=t/FH, c=t%FH;
    h[t]=x[(size_t)perm[i]*FH+c]*vals[i];
}
__global__ void k_scatadd(float* __restrict__ h,const int* __restrict__ perm,const float* __restrict__ xs,int tot,int f){
    int t=blockIdx.x*blockDim.x+threadIdx.x;
    if(t>=tot) return;
    int i=t/f, c=t%f;
    h[(size_t)perm[i]*f+c]+=xs[t];
}

// ---------------- layernorm ----------------
__global__ void k_ln(const float* __restrict__ h,const float* __restrict__ g,const float* __restrict__ b,float* __restrict__ u){
    __shared__ float red[128];
    int i=blockIdx.x, t=threadIdx.x;
    float v=h[(size_t)i*FO+t];
    red[t]=v; __syncthreads();
    for(int o=64;o;o>>=1){ if(t<o) red[t]+=red[t+o]; __syncthreads(); }
    float mu=red[0]/FO; __syncthreads();
    float d=v-mu;
    red[t]=d*d; __syncthreads();
    for(int o=64;o;o>>=1){ if(t<o) red[t]+=red[t+o]; __syncthreads(); }
    float var=red[0]/FO;
    u[(size_t)i*FO+t]=d*rsqrtf(var+1e-6f)*g[t]+b[t];
}

// ---------------- GAT (sparse, over csr0 incl. forced self loops) ----------------
__global__ void k_esed(const float* __restrict__ feat,const float* __restrict__ asrc,const float* __restrict__ adst,int heads,float* __restrict__ es,float* __restrict__ ed){
    int w=(blockIdx.x*blockDim.x+threadIdx.x)>>5;
    int lane=threadIdx.x&31;
    if(w>=N0) return;
    for(int h=0;h<heads;h++){
        float a=0.f,d=0.f;
        for(int c=lane;c<FO;c+=32){
            float f=feat[(size_t)w*(heads*FO)+h*FO+c];
            a+=f*asrc[h*FO+c];
            d+=f*adst[h*FO+c];
        }
        #pragma unroll
        for(int o=16;o;o>>=1){ a+=__shfl_xor_sync(0xffffffffu,a,o); d+=__shfl_xor_sync(0xffffffffu,d,o); }
        if(lane==0){ es[w*heads+h]=a; ed[w*heads+h]=d; }
    }
}

template<int HEADS>
__global__ void __launch_bounds__(128) k_gat(const float* __restrict__ feat,const float* __restrict__ es,const float* __restrict__ ed,float* __restrict__ out){
    __shared__ int snbr[MAXD0];
    __shared__ float salpha[MAXD0*HEADS];
    __shared__ float smax[HEADS], sinv[HEADS];
    int d=blockIdx.x, t=threadIdx.x;
    int cnt=g_cnt0[d];
    for(int i=t;i<cnt;i+=128) snbr[i]=g_idx0[(size_t)d*MAXD0+i];
    __syncthreads();
    for(int i=t;i<cnt;i+=128){
        int s=snbr[i];
        #pragma unroll
        for(int h=0;h<HEADS;h++){
            float l=ed[d*HEADS+h]+es[s*HEADS+h];
            l = (l>0.f)? l : 0.2f*l;
            salpha[i*HEADS+h]=l;
        }
    }
    __syncthreads();
    if(t<HEADS){
        float mx=-1e30f;
        for(int i=0;i<cnt;i++) mx=fmaxf(mx,salpha[i*HEADS+t]);
        float sm=0.f;
        for(int i=0;i<cnt;i++) sm+=expf(salpha[i*HEADS+t]-mx);
        smax[t]=mx; sinv[t]=1.f/sm;
    }
    __syncthreads();
    for(int i=t;i<cnt*HEADS;i+=128){
        int h=i%HEADS;
        salpha[i]=expf(salpha[i]-smax[h])*sinv[h];
    }
    __syncthreads();
    #pragma unroll
    for(int h=0;h<HEADS;h++){
        float acc=0.f;
        for(int i=0;i<cnt;i++)
            acc += salpha[i*HEADS+h]*feat[(size_t)snbr[i]*(HEADS*FO)+h*FO+t];
        out[(size_t)d*(HEADS*FO)+h*FO+t]=acc;
    }
}
__global__ void k_bias_elu(float* __restrict__ io,const float* __restrict__ b,int tot,int f){
    int t=blockIdx.x*blockDim.x+threadIdx.x;
    if(t>=tot) return;
    float v=io[t]+b[t%f];
    io[t]= (v>0.f)? v : expm1f(v);
}
__global__ void k_final(const float* __restrict__ g2,const float* __restrict__ g2b,
                        const float* __restrict__ res,const float* __restrict__ resb,
                        float* __restrict__ out,int tot,int f){
    int t=blockIdx.x*blockDim.x+threadIdx.x;
    if(t>=tot) return;
    out[t]=g2[t]+g2b[t%f]+res[t]+resb[t%f];
}

// ---------------- host orchestration ----------------
static inline int cdiv(int a,int b){return (a+b-1)/b;}

static void gemm(int M,int N,int K,const float*A,const float*B,float*C){
    if(N<=64 && M>=1024){
        dim3 g(cdiv(N,64),cdiv(M,32));
        sgemm_k<32,64,16,2,8><<<g,128>>>(M,N,K,A,B,C);
    } else {
        long b128=(long)cdiv(M,128)*cdiv(N,128);
        if(b128>=120){
            dim3 g(cdiv(N,128),cdiv(M,128));
            sgemm_k<128,128,16,8,8><<<g,256>>>(M,N,K,A,B,C);
        } else {
            dim3 g(cdiv(N,64),cdiv(M,64));
            sgemm_k<64,64,16,4,4><<<g,256>>>(M,N,K,A,B,C);
        }
    }
}

template<typename T> static T* symaddr(const void* sym){
    void* p=nullptr;
    cudaGetSymbolAddress(&p, sym);
    return (T*)p;
}

extern "C" void kernel_launch(void* const* d_in, const int* in_sizes, int n_in,
                              void* d_out, int out_size) {
    const float* x      =(const float*)d_in[0];
    const int*   ei     =(const int*  )d_in[1];
    const float* w0=(const float*)d_in[2],  *b0=(const float*)d_in[3];
    const float* w1=(const float*)d_in[4],  *b1=(const float*)d_in[5];
    const float* w2=(const float*)d_in[6],  *b2=(const float*)d_in[7];
    const float* w3=(const float*)d_in[8],  *b3=(const float*)d_in[9];
    const float* p1=(const float*)d_in[10], *p2=(const float*)d_in[11], *p3=(const float*)d_in[12];
    const float* uw0=(const float*)d_in[13],*ub0=(const float*)d_in[14];
    const float* uw1=(const float*)d_in[15],*ub1=(const float*)d_in[16];
    const float* uw2=(const float*)d_in[17],*ub2=(const float*)d_in[18];
    const float* lng=(const float*)d_in[19],*lnb=(const float*)d_in[20];
    const float* resw=(const float*)d_in[21],*resb=(const float*)d_in[22];
    const float* g1w=(const float*)d_in[23],*g1as=(const float*)d_in[24],*g1ad=(const float*)d_in[25],*g1b=(const float*)d_in[26];
    const float* g2w=(const float*)d_in[27],*g2as=(const float*)d_in[28],*g2ad=(const float*)d_in[29],*g2b=(const float*)d_in[30];

    float* A0=symaddr<float>(g_A0);
    int* idx0=symaddr<int>(g_idx0); float* val0=symaddr<float>(g_val0); int* cnt0=symaddr<int>(g_cnt0);
    int* idx1=symaddr<int>(g_idx1); float* val1=symaddr<float>(g_val1); int* cnt1=symaddr<int>(g_cnt1);
    int* idx2=symaddr<int>(g_idx2); float* val2=symaddr<float>(g_val2); int* cnt2=symaddr<int>(g_cnt2);
    int* idx3=symaddr<int>(g_idx3); float* val3=symaddr<float>(g_val3); int* cnt3=symaddr<int>(g_cnt3);
    float* Y=symaddr<float>(g_Y);   float* Z=symaddr<float>(g_Z);   float* S=symaddr<float>(g_S);
    float* x0b=symaddr<float>(g_x0);float* x1b=symaddr<float>(g_x1);
    float* x2b=symaddr<float>(g_x2);float* x3b=symaddr<float>(g_x3);
    float* hb=symaddr<float>(g_hbuf); float* upb=symaddr<float>(g_up);
    float* Hb=symaddr<float>(g_H);  float* Ub=symaddr<float>(g_U);  float* Rb=symaddr<float>(g_res);
    float* F1=symaddr<float>(g_feat1); float* GO=symaddr<float>(g_gout);
    float* di0=symaddr<float>(g_dinv0); float* df0=symaddr<float>(g_dfix0);
    float* di1=symaddr<float>(g_dinv1); float* di2=symaddr<float>(g_dinv2); float* di3=symaddr<float>(g_dinv3);
    float* sc=symaddr<float>(g_score);
    int* pm1=symaddr<int>(g_perm1); float* vl1=symaddr<float>(g_vals1);
    int* pm2=symaddr<int>(g_perm2); float* vl2=symaddr<float>(g_vals2);
    int* pm3=symaddr<int>(g_perm3); float* vl3=symaddr<float>(g_vals3);
    int* ipos=symaddr<int>(g_ipos);
    float* ES=symaddr<float>(g_es); float* ED=symaddr<float>(g_ed);
    float* out=(float*)d_out;

    // generic GCN over a CSR level
    auto gcn=[&](int n,const int* idx,const float* val,const int* cnt,int maxd,
                 const float* hin,int kin,const float* W,int kout,const float* b,
                 const float* dinv,const float* dfix,float* xout,bool relu){
        gemm(n,kout,kin,hin,W,Y);
        int tot=n*kout;
        k_scale<<<cdiv(tot,256),256>>>(Y,dinv,tot,kout,Z);
        if(kout==64) k_spmm<64><<<cdiv(n*64,256),256>>>(n,idx,val,cnt,maxd,Z,dinv,dfix,b,xout,relu?1:0);
        else         k_spmm<128><<<cdiv(n*128,256),256>>>(n,idx,val,cnt,maxd,Z,dinv,dfix,b,xout,relu?1:0);
    };

    // ---- build A0 + CSR0 ----
    cudaMemsetAsync(A0,0,(size_t)N0*N0*sizeof(float),0);
    k_buildA0<<<cdiv(NE,256),256>>>(ei,A0);
    k_csr0<<<cdiv(N0,8),256>>>(A0,idx0,val0,cnt0,di0,df0);

    // ---- down path ----
    gcn(N0,idx0,val0,cnt0,MAXD0, x,3, w0,FH,b0, di0,df0, x0b,true);

    // pool1
    k_score<<<cdiv(N0,8),256>>>(x0b,p1,N0,sc);
    k_sort<<<1,1024>>>(sc,N0,N1,pm1,vl1);
    cudaMemsetAsync(ipos,0xFF,N0*sizeof(int),0);
    k_iposset<<<cdiv(N1,256),256>>>(pm1,N1,ipos);
    k_spgemm<N1,true><<<N1,256>>>(idx0,val0,cnt0,MAXD0,pm1,ipos,idx1,val1,cnt1,MAXD1,di1);
    k_poolgather<<<cdiv(N1*FH,256),256>>>(x0b,pm1,vl1,N1*FH,hb);

    gcn(N1,idx1,val1,cnt1,MAXD1, hb,FH, w1,FH,b1, di1,nullptr, x1b,true);

    // pool2
    k_score<<<cdiv(N1,8),256>>>(x1b,p2,N1,sc);
    k_sort<<<1,1024>>>(sc,N1,N2,pm2,vl2);
    cudaMemsetAsync(ipos,0xFF,N1*sizeof(int),0);
    k_iposset<<<cdiv(N2,256),256>>>(pm2,N2,ipos);
    k_spgemm<N2,false><<<N2,256>>>(idx1,val1,cnt1,MAXD1,pm2,ipos,idx2,val2,cnt2,MAXD2,di2);
    k_poolgather<<<cdiv(N2*FH,256),256>>>(x1b,pm2,vl2,N2*FH,hb);

    gcn(N2,idx2,val2,cnt2,MAXD2, hb,FH, w2,FH,b2, di2,nullptr, x2b,true);

    // pool3
    k_score<<<cdiv(N2,8),256>>>(x2b,p3,N2,sc);
    k_sort<<<1,1024>>>(sc,N2,N3,pm3,vl3);
    cudaMemsetAsync(ipos,0xFF,N2*sizeof(int),0);
    k_iposset<<<cdiv(N3,256),256>>>(pm3,N3,ipos);
    k_spgemm<N3,false><<<N3,256>>>(idx2,val2,cnt2,MAXD2,pm3,ipos,idx3,val3,cnt3,MAXD3,di3);
    k_poolgather<<<cdiv(N3*FH,256),256>>>(x2b,pm3,vl3,N3*FH,hb);

    gcn(N3,idx3,val3,cnt3,MAXD3, hb,FH, w3,FH,b3, di3,nullptr, x3b,true);

    // ---- up path ----
    cudaMemcpyAsync(hb,x2b,(size_t)N2*FH*sizeof(float),cudaMemcpyDeviceToDevice,0);
    k_scatadd<<<cdiv(N3*FH,256),256>>>(hb,pm3,x3b,N3*FH,FH);
    gcn(N2,idx2,val2,cnt2,MAXD2, hb,FH, uw0,FH,ub0, di2,nullptr, upb,true);

    cudaMemcpyAsync(hb,x1b,(size_t)N1*FH*sizeof(float),cudaMemcpyDeviceToDevice,0);
    k_scatadd<<<cdiv(N2*FH,256),256>>>(hb,pm2,upb,N2*FH,FH);
    gcn(N1,idx1,val1,cnt1,MAXD1, hb,FH, uw1,FH,ub1, di1,nullptr, upb,true);

    cudaMemcpyAsync(hb,x0b,(size_t)N0*FH*sizeof(float),cudaMemcpyDeviceToDevice,0);
    k_scatadd<<<cdiv(N1*FH,256),256>>>(hb,pm1,upb,N1*FH,FH);
    gcn(N0,idx0,val0,cnt0,MAXD0, hb,FH, uw2,FO,ub2, di0,df0, Hb,false);

    // ---- layernorm + residual ----
    k_ln<<<N0,128>>>(Hb,lng,lnb,Ub);
    gemm(N0,FO,FO,Ub,resw,Rb);

    // ---- GAT layers (sparse over csr0) ----
    gemm(N0,4*FO,FO,Ub,g1w,F1);
    k_esed<<<cdiv(N0,8),256>>>(F1,g1as,g1ad,4,ES,ED);
    k_gat<4><<<N0,128>>>(F1,ES,ED,GO);
    k_bias_elu<<<cdiv(N0*4*FO,256),256>>>(GO,g1b,N0*4*FO,4*FO);

    gemm(N0,FO,4*FO,GO,g2w,S);
    k_esed<<<cdiv(N0,8),256>>>(S,g2as,g2ad,1,ES,ED);
    k_gat<1><<<N0,128>>>(S,ES,ED,Y);

    k_final<<<cdiv(N0*FO,256),256>>>(Y,g2b,Rb,resb,out,N0*FO,FO);
}

// round 3
// speedup vs baseline: 2.8658x; 1.9821x over previous
#include <cuda_runtime.h>
#include <cuda_bf16.h>
#include <math.h>

// ---------------- problem constants ----------------
#define N0 4096
#define N1 2048
#define N2 1024
#define N3 512
#define NE 65536
#define FH 64
#define FO 128
#define MAXD0 128
#define MAXD1 2048

// ---------------- static device scratch ----------------
__device__ float g_A0[(size_t)N0*N0];
__device__ int   g_idx0[(size_t)N0*MAXD0]; __device__ float g_val0[(size_t)N0*MAXD0];
__device__ float g_val0s[(size_t)N0*MAXD0]; __device__ int g_cnt0[N0];
__device__ int   g_idx1[(size_t)N1*MAXD1]; __device__ float g_val1[(size_t)N1*MAXD1];
__device__ float g_val1s[(size_t)N1*MAXD1]; __device__ int g_cnt1[N1];
__device__ float g_A2d[(size_t)N2*N2];
__device__ float g_A2h[(size_t)N2*N2];
__device__ float g_A3d[(size_t)N3*N3];
__device__ float g_A3h[(size_t)N3*N3];
__device__ float g_Rg[(size_t)N3*N2];
__device__ float g_Cg[(size_t)N2*N3];
__device__ float g_Y[(size_t)N0*FO];
__device__ float g_S[(size_t)N0*FO];
__device__ float g_x0[N0*FH], g_x1[N1*FH], g_x2[N2*FH], g_x3[N3*FH];
__device__ float g_hbuf[N0*FH];
__device__ float g_up[N1*FH];
__device__ float g_H[N0*FO];
__device__ float g_U[N0*FO];
__device__ float g_res[N0*FO];
__device__ float g_feat1[(size_t)N0*512];
__device__ float g_gout[(size_t)N0*512];
__device__ float g_dinv0[N0], g_dfix0[N0];
__device__ float g_dinv1[N1], g_dinv2[N2], g_dinv3[N3];
__device__ int   g_perm1[N1]; __device__ float g_vals1[N1];
__device__ int   g_perm2[N2]; __device__ float g_vals2[N2];
__device__ int   g_perm3[N3]; __device__ float g_vals3[N3];
__device__ int   g_ipos1[N0], g_ipos2[N1], g_ipos3[N2];
__device__ float g_es[N0*4], g_ed[N0*4];

// ---------------- generic SGEMM ----------------
template<int BM,int BN,int BK,int TM,int TN>
__global__ void __launch_bounds__((BM/TM)*(BN/TN))
sgemm_k(int M,int N,int K,const float* __restrict__ A,const float* __restrict__ B,float* __restrict__ C){
    constexpr int THREADS=(BM/TM)*(BN/TN);
    __shared__ float As[BK][BM+1];
    __shared__ float Bs[BK][BN];
    const int bm = blockIdx.y*BM, bn = blockIdx.x*BN;
    const int tid = threadIdx.x;
    const int tcol = tid % (BN/TN);
    const int trow = tid / (BN/TN);
    float acc[TM][TN];
    #pragma unroll
    for(int i=0;i<TM;i++)
        #pragma unroll
        for(int j=0;j<TN;j++) acc[i][j]=0.f;
    for(int k0=0;k0<K;k0+=BK){
        #pragma unroll 4
        for(int i=tid;i<BM*BK;i+=THREADS){
            int m=i/BK, k=i%BK;
            int gm=bm+m, gk=k0+k;
            float v=0.f;
            if(gm<M && gk<K) v=A[(size_t)gm*K+gk];
            As[k][m]=v;
        }
        #pragma unroll 4
        for(int i=tid;i<BK*BN;i+=THREADS){
            int k=i/BN, n=i%BN;
            int gk=k0+k, gn=bn+n;
            float v=0.f;
            if(gk<K && gn<N) v=B[(size_t)gk*N+gn];
            Bs[k][n]=v;
        }
        __syncthreads();
        #pragma unroll
        for(int kk=0;kk<BK;kk++){
            float ra[TM], rb[TN];
            #pragma unroll
            for(int i=0;i<TM;i++) ra[i]=As[kk][trow*TM+i];
            #pragma unroll
            for(int j=0;j<TN;j++) rb[j]=Bs[kk][tcol*TN+j];
            #pragma unroll
            for(int i=0;i<TM;i++)
                #pragma unroll
                for(int j=0;j<TN;j++) acc[i][j]+=ra[i]*rb[j];
        }
        __syncthreads();
    }
    #pragma unroll
    for(int i=0;i<TM;i++){
        int gm=bm+trow*TM+i;
        if(gm>=M) continue;
        #pragma unroll
        for(int j=0;j<TN;j++){
            int gn=bn+tcol*TN+j;
            if(gn<N) C[(size_t)gm*N+gn]=acc[i][j];
        }
    }
}

// ---------------- graph build ----------------
__global__ void k_buildA0(const int* __restrict__ ei, float* __restrict__ A){
    int e = blockIdx.x*blockDim.x+threadIdx.x;
    if(e<NE){
        int s=ei[e];
        int d=ei[NE+e];
        atomicAdd(&A[(size_t)d*N0+s], 1.0f);
    }
}

__global__ void k_csr0(const float* __restrict__ A,int* __restrict__ idx,float* __restrict__ val,
                       int* __restrict__ cnt,float* __restrict__ dinv,float* __restrict__ dfix){
    int w=(blockIdx.x*blockDim.x+threadIdx.x)>>5;
    int lane=threadIdx.x&31;
    if(w>=N0) return;
    const float* row=A+(size_t)w*N0;
    int c=0; float rs=0.f;
    for(int base=0;base<N0;base+=32){
        int s=base+lane;
        float v=row[s];
        bool p=(v!=0.f)||(s==w);
        unsigned m=__ballot_sync(0xffffffffu,p);
        if(p){
            int off=c+__popc(m&((1u<<lane)-1u));
            idx[(size_t)w*MAXD0+off]=s;
            val[(size_t)w*MAXD0+off]=v;
            rs+=v;
        }
        c+=__popc(m);
    }
    #pragma unroll
    for(int o=16;o;o>>=1) rs+=__shfl_xor_sync(0xffffffffu,rs,o);
    if(lane==0){
        float d=row[w];
        float fx=(d==0.f)?2.f:0.f;
        cnt[w]=c;
        dfix[w]=fx;
        dinv[w]=rsqrtf(rs+fx);
    }
}

// val_out[e] = val[e]*dinv[r]*dinv[col]
__global__ void k_prescale_csr(int n,const int* __restrict__ idx,const float* __restrict__ val,
                               const int* __restrict__ cnt,int maxd,const float* __restrict__ dinv,
                               float* __restrict__ valo){
    int w=(blockIdx.x*blockDim.x+threadIdx.x)>>5;
    int lane=threadIdx.x&31;
    if(w>=n) return;
    float dr=dinv[w];
    int cn=cnt[w];
    for(int e=lane;e<cn;e+=32)
        valo[(size_t)w*maxd+e]=val[(size_t)w*maxd+e]*dr*dinv[idx[(size_t)w*maxd+e]];
}

// ---------------- GCN ----------------
// fused CSR SpMM + epilogue. vals pre-scaled by dinv_r*dinv_c.
template<int F>
__global__ void k_spmmf(int n,const int* __restrict__ idx,const float* __restrict__ val,
                        const int* __restrict__ cnt,int maxd,
                        const float* __restrict__ Y,const float* __restrict__ dinv,
                        const float* __restrict__ dfix,const float* __restrict__ b,
                        float* __restrict__ out,int relu){
    int r = blockIdx.x*(256/F) + threadIdx.x/F;
    int c = threadIdx.x%F;
    if(r>=n) return;
    int cn=cnt[r];
    const int* ip=idx+(size_t)r*maxd;
    const float* vp=val+(size_t)r*maxd;
    float acc=0.f;
    for(int e=0;e<cn;e++)
        acc += vp[e]*Y[(size_t)ip[e]*F+c];
    float fx = dfix? dfix[r] : 2.0f;
    float di = dinv[r];
    float v = acc + fx*di*di*Y[(size_t)r*F+c] + b[c];
    out[(size_t)r*F+c] = relu? fmaxf(v,0.f) : v;
}

// dense GCN epilogue: out = S + 2*di^2*Y + b
__global__ void k_gcnepd(const float* __restrict__ S,const float* __restrict__ Y,
                         const float* __restrict__ dinv,const float* __restrict__ b,
                         float* __restrict__ out,int tot,int f,int relu){
    int t=blockIdx.x*blockDim.x+threadIdx.x;
    if(t>=tot) return;
    int r=t/f;
    float di=dinv[r];
    float v = S[t] + 2.f*di*di*Y[t] + b[t%f];
    out[t] = relu? fmaxf(v,0.f) : v;
}

// ---------------- fused pool: score + bitonic topk + ipos + gather ----------------
template<int N>
__global__ void __launch_bounds__(1024) k_pool(const float* __restrict__ x,const float* __restrict__ p,
                                               int k,int* __restrict__ perm,float* __restrict__ vals,
                                               int* __restrict__ ipos,float* __restrict__ h){
    __shared__ float kk[N];
    __shared__ int   ii[N];
    int t=threadIdx.x;
    float pn=0.f;
    #pragma unroll
    for(int c=0;c<FH;c++){ float pv=p[c]; pn+=pv*pv; }
    float rn=rsqrtf(pn);
    for(int r=t;r<N;r+=1024){
        float d=0.f;
        #pragma unroll
        for(int c=0;c<FH;c++) d+=x[(size_t)r*FH+c]*p[c];
        kk[r]=tanhf(d*rn);
        ii[r]=r;
    }
    __syncthreads();
    for(int size=2;size<=N;size<<=1){
        for(int stride=size>>1;stride>0;stride>>=1){
            for(int i=t;i<(N>>1);i+=1024){
                int lo = 2*i - (i&(stride-1));
                int hi = lo+stride;
                bool up = ((lo & size)==0);
                float ka=kk[lo], kb=kk[hi];
                int ia=ii[lo], ib=ii[hi];
                bool beforeBA = (kb>ka) || (kb==ka && ib<ia);
                bool sw = up ? beforeBA : !beforeBA;
                if(sw){ kk[lo]=kb;kk[hi]=ka;ii[lo]=ib;ii[hi]=ia; }
            }
            __syncthreads();
        }
    }
    for(int i=t;i<N;i+=1024) ipos[ii[i]] = (i<k)? i : -1;
    for(int i=t;i<k;i+=1024){ perm[i]=ii[i]; vals[i]=kk[i]; }
    for(int idx=t;idx<k*FH;idx+=1024){
        int i=idx/FH, c=idx%FH;
        h[idx]=x[(size_t)ii[i]*FH+c]*kk[i];
    }
}

// ---------------- SpGEMM level1 (CSR out) ----------------
template<int NCOL>
__global__ void __launch_bounds__(256) k_spgemm_csr(
        const int* __restrict__ inIdx,const float* __restrict__ inVal,const int* __restrict__ inCnt,int inMaxd,
        const int* __restrict__ perm,const int* __restrict__ ipos,
        int* __restrict__ outIdx,float* __restrict__ outVal,int* __restrict__ outCnt,int outMaxd,
        float* __restrict__ dinv){
    __shared__ float acc[NCOL];
    int i=blockIdx.x, t=threadIdx.x;
    for(int j=t;j<NCOL;j+=256) acc[j]=0.f;
    __syncthreads();
    int r0=perm[i];
    int cr=inCnt[r0];
    const int* rip=inIdx+(size_t)r0*inMaxd;
    const float* rvp=inVal+(size_t)r0*inMaxd;
    int warp=t>>5, lane=t&31;
    for(int e=warp;e<cr;e+=8){
        int k=rip[e];
        float rv=rvp[e] + ((k==r0)?1.f:0.f);
        int ck=inCnt[k];
        const int* kip=inIdx+(size_t)k*inMaxd;
        const float* kvp=inVal+(size_t)k*inMaxd;
        for(int f=lane;f<ck;f+=32){
            int s=kip[f];
            float cv=kvp[f] + ((s==k)?1.f:0.f);
            int j=ipos[s];
            if(j>=0) atomicAdd(&acc[j], rv*cv);
        }
    }
    __syncthreads();
    if(t==0) acc[i]=0.f;
    __syncthreads();
    if(warp==0){
        int c=0; float rs=0.f;
        for(int base=0;base<NCOL;base+=32){
            int j=base+lane;
            float v=acc[j];
            bool p=(v!=0.f);
            unsigned m=__ballot_sync(0xffffffffu,p);
            if(p){
                int off=c+__popc(m&((1u<<lane)-1u));
                outIdx[(size_t)i*outMaxd+off]=j;
                outVal[(size_t)i*outMaxd+off]=v;
                rs+=v;
            }
            c+=__popc(m);
        }
        #pragma unroll
        for(int o=16;o;o>>=1) rs+=__shfl_xor_sync(0xffffffffu,rs,o);
        if(lane==0){ outCnt[i]=c; dinv[i]=rsqrtf(rs+2.f); }
    }
}

// ---------------- SpGEMM level2 (dense out, input CSR has NO diag) ----------------
template<int NCOL>
__global__ void __launch_bounds__(256) k_spgemm_dense(
        const int* __restrict__ inIdx,const float* __restrict__ inVal,const int* __restrict__ inCnt,int inMaxd,
        const int* __restrict__ perm,const int* __restrict__ ipos,
        float* __restrict__ outD,float* __restrict__ dinv){
    __shared__ float acc[NCOL];
    __shared__ float red[8];
    int i=blockIdx.x, t=threadIdx.x;
    for(int j=t;j<NCOL;j+=256) acc[j]=0.f;
    __syncthreads();
    int r0=perm[i];
    int cr=inCnt[r0];
    int total=cr+1;
    const int* rip=inIdx+(size_t)r0*inMaxd;
    const float* rvp=inVal+(size_t)r0*inMaxd;
    int warp=t>>5, lane=t&31;
    for(int e=warp;e<total;e+=8){
        int k; float rv;
        if(e<cr){ k=rip[e]; rv=rvp[e]; }
        else    { k=r0; rv=1.f; }
        int ck=inCnt[k];
        const int* kip=inIdx+(size_t)k*inMaxd;
        const float* kvp=inVal+(size_t)k*inMaxd;
        int tot2=ck+1;
        for(int f=lane;f<tot2;f+=32){
            int s; float cv;
            if(f<ck){ s=kip[f]; cv=kvp[f]; }
            else    { s=k; cv=1.f; }
            int j=ipos[s];
            if(j>=0) atomicAdd(&acc[j], rv*cv);
        }
    }
    __syncthreads();
    if(t==0) acc[i]=0.f;
    __syncthreads();
    float rs=0.f;
    for(int j=t;j<NCOL;j+=256){ rs+=acc[j]; outD[(size_t)i*NCOL+j]=acc[j]; }
    #pragma unroll
    for(int o=16;o;o>>=1) rs+=__shfl_xor_sync(0xffffffffu,rs,o);
    if(lane==0) red[warp]=rs;
    __syncthreads();
    if(t==0){
        float s=0.f;
        #pragma unroll
        for(int w=0;w<8;w++) s+=red[w];
        dinv[i]=rsqrtf(s+2.f);
    }
}

// ---------------- level-3 dense helpers ----------------
__global__ void k_gatherR(const float* __restrict__ A,int n,const int* __restrict__ perm,int m,float* __restrict__ R){
    size_t t=(size_t)blockIdx.x*blockDim.x+threadIdx.x;
    if(t>=(size_t)m*n) return;
    int i=(int)(t/n), k=(int)(t%n);
    int pi=perm[i];
    R[t]=A[(size_t)pi*n+k] + ((k==pi)?1.f:0.f);
}
__global__ void k_gatherC(const float* __restrict__ A,int n,const int* __restrict__ perm,int m,float* __restrict__ C){
    size_t t=(size_t)blockIdx.x*blockDim.x+threadIdx.x;
    if(t>=(size_t)m*n) return;
    int k=(int)(t/m), j=(int)(t%m);
    int pj=perm[j];
    C[t]=A[(size_t)k*n+pj] + ((k==pj)?1.f:0.f);
}
// zero diag + rowsum -> dinv   (block per row)
__global__ void __launch_bounds__(256) k_finishA3(float* __restrict__ A,int m,float* __restrict__ dinv){
    __shared__ float red[8];
    int r=blockIdx.x, t=threadIdx.x;
    if(t==0) A[(size_t)r*m+r]=0.f;
    __syncthreads();
    float s=0.f;
    for(int j=t;j<m;j+=256) s+=A[(size_t)r*m+j];
    #pragma unroll
    for(int o=16;o;o>>=1) s+=__shfl_xor_sync(0xffffffffu,s,o);
    if((t&31)==0) red[t>>5]=s;
    __syncthreads();
    if(t==0){
        float ss=0.f;
        #pragma unroll
        for(int w=0;w<8;w++) ss+=red[w];
        dinv[r]=rsqrtf(ss+2.f);
    }
}
__global__ void k_prescale_dense(const float* __restrict__ A,int m,const float* __restrict__ dinv,float* __restrict__ O){
    size_t t=(size_t)blockIdx.x*blockDim.x+threadIdx.x;
    if(t>=(size_t)m*m) return;
    int r=(int)(t/m), c=(int)(t%m);
    O[t]=A[t]*dinv[r]*dinv[c];
}

// up-merge: h = x_fine + scatter(xs at perm) via inverse perm
__global__ void k_upmerge(const float* __restrict__ xf,const int* __restrict__ ipos,
                          const float* __restrict__ xs,float* __restrict__ h,int tot){
    int t=blockIdx.x*blockDim.x+threadIdx.x;
    if(t>=tot) return;
    int r=t/FH;
    int j=ipos[r];
    float v=xf[t];
    if(j>=0) v+=xs[(size_t)j*FH + (t%FH)];
    h[t]=v;
}

// ---------------- layernorm ----------------
__global__ void k_ln(const float* __restrict__ h,const float* __restrict__ g,const float* __restrict__ b,float* __restrict__ u){
    __shared__ float red[128];
    int i=blockIdx.x, t=threadIdx.x;
    float v=h[(size_t)i*FO+t];
    red[t]=v; __syncthreads();
    for(int o=64;o;o>>=1){ if(t<o) red[t]+=red[t+o]; __syncthreads(); }
    float mu=red[0]/FO; __syncthreads();
    float d=v-mu;
    red[t]=d*d; __syncthreads();
    for(int o=64;o;o>>=1){ if(t<o) red[t]+=red[t+o]; __syncthreads(); }
    float var=red[0]/FO;
    u[(size_t)i*FO+t]=d*rsqrtf(var+1e-6f)*g[t]+b[t];
}

// ---------------- GAT ----------------
__global__ void k_esed(const float* __restrict__ feat,const float* __restrict__ asrc,const float* __restrict__ adst,int heads,float* __restrict__ es,float* __restrict__ ed){
    int w=(blockIdx.x*blockDim.x+threadIdx.x)>>5;
    int lane=threadIdx.x&31;
    if(w>=N0) return;
    for(int h=0;h<heads;h++){
        float a=0.f,d=0.f;
        for(int c=lane;c<FO;c+=32){
            float f=feat[(size_t)w*(heads*FO)+h*FO+c];
            a+=f*asrc[h*FO+c];
            d+=f*adst[h*FO+c];
        }
        #pragma unroll
        for(int o=16;o;o>>=1){ a+=__shfl_xor_sync(0xffffffffu,a,o); d+=__shfl_xor_sync(0xffffffffu,d,o); }
        if(lane==0){ es[w*heads+h]=a; ed[w*heads+h]=d; }
    }
}

// MODE 0: out = elu(acc + bias).  MODE 1: out = acc + bias + res + resb (final).
template<int HEADS,int MODE>
__global__ void __launch_bounds__(128) k_gat(const float* __restrict__ feat,const float* __restrict__ es,const float* __restrict__ ed,
                                             const float* __restrict__ bias,const float* __restrict__ res,const float* __restrict__ resb,
                                             float* __restrict__ out){
    __shared__ int snbr[MAXD0];
    __shared__ float salpha[MAXD0*HEADS];
    __shared__ float smax[HEADS], sinv[HEADS];
    int d=blockIdx.x, t=threadIdx.x;
    int cnt=g_cnt0[d];
    for(int i=t;i<cnt;i+=128) snbr[i]=g_idx0[(size_t)d*MAXD0+i];
    __syncthreads();
    for(int i=t;i<cnt;i+=128){
        int s=snbr[i];
        #pragma unroll
        for(int h=0;h<HEADS;h++){
            float l=ed[d*HEADS+h]+es[s*HEADS+h];
            l = (l>0.f)? l : 0.2f*l;
            salpha[i*HEADS+h]=l;
        }
    }
    __syncthreads();
    if(t<HEADS){
        float mx=-1e30f;
        for(int i=0;i<cnt;i++) mx=fmaxf(mx,salpha[i*HEADS+t]);
        float sm=0.f;
        for(int i=0;i<cnt;i++) sm+=expf(salpha[i*HEADS+t]-mx);
        smax[t]=mx; sinv[t]=1.f/sm;
    }
    __syncthreads();
    for(int i=t;i<cnt*HEADS;i+=128){
        int h=i%HEADS;
        salpha[i]=expf(salpha[i]-smax[h])*sinv[h];
    }
    __syncthreads();
    #pragma unroll
    for(int h=0;h<HEADS;h++){
        float acc=0.f;
        for(int i=0;i<cnt;i++)
            acc += salpha[i*HEADS+h]*feat[(size_t)snbr[i]*(HEADS*FO)+h*FO+t];
        if(MODE==0){
            float v=acc+bias[h*FO+t];
            out[(size_t)d*(HEADS*FO)+h*FO+t]= (v>0.f)? v : expm1f(v);
        } else {
            out[(size_t)d*FO+t]=acc+bias[t]+res[(size_t)d*FO+t]+resb[t];
        }
    }
}

// ---------------- host ----------------
static inline int cdiv(int a,int b){return (a+b-1)/b;}

static void gemm(int M,int N,int K,const float*A,const float*B,float*C){
    if(N<=64 && M>=512){
        dim3 g(cdiv(N,64),cdiv(M,32));
        sgemm_k<32,64,16,2,8><<<g,128>>>(M,N,K,A,B,C);
    } else {
        long b128=(long)cdiv(M,128)*cdiv(N,128);
        if(b128>=120){
            dim3 g(cdiv(N,128),cdiv(M,128));
            sgemm_k<128,128,16,8,8><<<g,256>>>(M,N,K,A,B,C);
        } else {
            dim3 g(cdiv(N,64),cdiv(M,64));
            sgemm_k<64,64,16,4,4><<<g,256>>>(M,N,K,A,B,C);
        }
    }
}

template<typename T> static T* symaddr(const void* sym){
    void* p=nullptr;
    cudaGetSymbolAddress(&p, sym);
    return (T*)p;
}

extern "C" void kernel_launch(void* const* d_in, const int* in_sizes, int n_in,
                              void* d_out, int out_size) {
    const float* x      =(const float*)d_in[0];
    const int*   ei     =(const int*  )d_in[1];
    const float* w0=(const float*)d_in[2],  *b0=(const float*)d_in[3];
    const float* w1=(const float*)d_in[4],  *b1=(const float*)d_in[5];
    const float* w2=(const float*)d_in[6],  *b2=(const float*)d_in[7];
    const float* w3=(const float*)d_in[8],  *b3=(const float*)d_in[9];
    const float* p1=(const float*)d_in[10], *p2=(const float*)d_in[11], *p3=(const float*)d_in[12];
    const float* uw0=(const float*)d_in[13],*ub0=(const float*)d_in[14];
    const float* uw1=(const float*)d_in[15],*ub1=(const float*)d_in[16];
    const float* uw2=(const float*)d_in[17],*ub2=(const float*)d_in[18];
    const float* lng=(const float*)d_in[19],*lnb=(const float*)d_in[20];
    const float* resw=(const float*)d_in[21],*resb=(const float*)d_in[22];
    const float* g1w=(const float*)d_in[23],*g1as=(const float*)d_in[24],*g1ad=(const float*)d_in[25],*g1b=(const float*)d_in[26];
    const float* g2w=(const float*)d_in[27],*g2as=(const float*)d_in[28],*g2ad=(const float*)d_in[29],*g2b=(const float*)d_in[30];

    float* A0=symaddr<float>(g_A0);
    int* idx0=symaddr<int>(g_idx0); float* val0=symaddr<float>(g_val0);
    float* val0s=symaddr<float>(g_val0s); int* cnt0=symaddr<int>(g_cnt0);
    int* idx1=symaddr<int>(g_idx1); float* val1=symaddr<float>(g_val1);
    float* val1s=symaddr<float>(g_val1s); int* cnt1=symaddr<int>(g_cnt1);
    float* A2d=symaddr<float>(g_A2d); float* A2h=symaddr<float>(g_A2h);
    float* A3d=symaddr<float>(g_A3d); float* A3h=symaddr<float>(g_A3h);
    float* Rg=symaddr<float>(g_Rg); float* Cg=symaddr<float>(g_Cg);
    float* Y=symaddr<float>(g_Y);   float* S=symaddr<float>(g_S);
    float* x0b=symaddr<float>(g_x0);float* x1b=symaddr<float>(g_x1);
    float* x2b=symaddr<float>(g_x2);float* x3b=symaddr<float>(g_x3);
    float* hb=symaddr<float>(g_hbuf); float* upb=symaddr<float>(g_up);
    float* Hb=symaddr<float>(g_H);  float* Ub=symaddr<float>(g_U);  float* Rb=symaddr<float>(g_res);
    float* F1=symaddr<float>(g_feat1); float* GO=symaddr<float>(g_gout);
    float* di0=symaddr<float>(g_dinv0); float* df0=symaddr<float>(g_dfix0);
    float* di1=symaddr<float>(g_dinv1); float* di2=symaddr<float>(g_dinv2); float* di3=symaddr<float>(g_dinv3);
    int* pm1=symaddr<int>(g_perm1); float* vl1=symaddr<float>(g_vals1);
    int* pm2=symaddr<int>(g_perm2); float* vl2=symaddr<float>(g_vals2);
    int* pm3=symaddr<int>(g_perm3); float* vl3=symaddr<float>(g_vals3);
    int* ip1=symaddr<int>(g_ipos1); int* ip2=symaddr<int>(g_ipos2); int* ip3=symaddr<int>(g_ipos3);
    float* ES=symaddr<float>(g_es); float* ED=symaddr<float>(g_ed);
    float* out=(float*)d_out;

    // ---- build A0 + CSR0 + prescale ----
    cudaMemsetAsync(A0,0,(size_t)N0*N0*sizeof(float),0);
    k_buildA0<<<cdiv(NE,256),256>>>(ei,A0);
    k_csr0<<<cdiv(N0,8),256>>>(A0,idx0,val0,cnt0,di0,df0);
    k_prescale_csr<<<cdiv(N0,8),256>>>(N0,idx0,val0,cnt0,MAXD0,di0,val0s);

    // ---- gcn0 down ----
    gemm(N0,FH,3,x,w0,Y);
    k_spmmf<64><<<cdiv(N0*64,256),256>>>(N0,idx0,val0s,cnt0,MAXD0,Y,di0,df0,b0,x0b,1);

    // ---- pool1 + A1 (sparse) ----
    k_pool<N0><<<1,1024>>>(x0b,p1,N1,pm1,vl1,ip1,hb);
    k_spgemm_csr<N1><<<N1,256>>>(idx0,val0,cnt0,MAXD0,pm1,ip1,idx1,val1,cnt1,MAXD1,di1);
    k_prescale_csr<<<cdiv(N1,8),256>>>(N1,idx1,val1,cnt1,MAXD1,di1,val1s);

    // ---- gcn1 down ----
    gemm(N1,FH,FH,hb,w1,Y);
    k_spmmf<64><<<cdiv(N1*64,256),256>>>(N1,idx1,val1s,cnt1,MAXD1,Y,di1,nullptr,b1,x1b,1);

    // ---- pool2 + A2 (dense out) ----
    k_pool<N1><<<1,1024>>>(x1b,p2,N2,pm2,vl2,ip2,hb);
    k_spgemm_dense<N2><<<N2,256>>>(idx1,val1,cnt1,MAXD1,pm2,ip2,A2d,di2);
    k_prescale_dense<<<cdiv(N2*N2,256),256>>>(A2d,N2,di2,A2h);

    // ---- gcn2 down (dense) ----
    gemm(N2,FH,FH,hb,w2,Y);
    gemm(N2,FH,N2,A2h,Y,S);
    k_gcnepd<<<cdiv(N2*FH,256),256>>>(S,Y,di2,b2,x2b,N2*FH,FH,1);

    // ---- pool3 + A3 (dense GEMM) ----
    k_pool<N2><<<1,1024>>>(x2b,p3,N3,pm3,vl3,ip3,hb);
    k_gatherR<<<cdiv(N3*N2,256),256>>>(A2d,N2,pm3,N3,Rg);
    k_gatherC<<<cdiv(N3*N2,256),256>>>(A2d,N2,pm3,N3,Cg);
    gemm(N3,N3,N2,Rg,Cg,A3d);
    k_finishA3<<<N3,256>>>(A3d,N3,di3);
    k_prescale_dense<<<cdiv(N3*N3,256),256>>>(A3d,N3,di3,A3h);

    // ---- gcn3 down (dense) ----
    gemm(N3,FH,FH,hb,w3,Y);
    gemm(N3,FH,N3,A3h,Y,S);
    k_gcnepd<<<cdiv(N3*FH,256),256>>>(S,Y,di3,b3,x3b,N3*FH,FH,1);

    // ---- up path ----
    k_upmerge<<<cdiv(N2*FH,256),256>>>(x2b,ip3,x3b,hb,N2*FH);
    gemm(N2,FH,FH,hb,uw0,Y);
    gemm(N2,FH,N2,A2h,Y,S);
    k_gcnepd<<<cdiv(N2*FH,256),256>>>(S,Y,di2,ub0,upb,N2*FH,FH,1);

    k_upmerge<<<cdiv(N1*FH,256),256>>>(x1b,ip2,upb,hb,N1*FH);
    gemm(N1,FH,FH,hb,uw1,Y);
    k_spmmf<64><<<cdiv(N1*64,256),256>>>(N1,idx1,val1s,cnt1,MAXD1,Y,di1,nullptr,ub1,upb,1);

    k_upmerge<<<cdiv(N0*FH,256),256>>>(x0b,ip1,upb,hb,N0*FH);
    gemm(N0,FO,FH,hb,uw2,Y);
    k_spmmf<128><<<cdiv(N0*128,256),256>>>(N0,idx0,val0s,cnt0,MAXD0,Y,di0,df0,ub2,Hb,0);

    // ---- layernorm + residual ----
    k_ln<<<N0,128>>>(Hb,lng,lnb,Ub);
    gemm(N0,FO,FO,Ub,resw,Rb);

    // ---- GAT layers ----
    gemm(N0,4*FO,FO,Ub,g1w,F1);
    k_esed<<<cdiv(N0,8),256>>>(F1,g1as,g1ad,4,ES,ED);
    k_gat<4,0><<<N0,128>>>(F1,ES,ED,g1b,nullptr,nullptr,GO);

    gemm(N0,FO,4*FO,GO,g2w,S);
    k_esed<<<cdiv(N0,8),256>>>(S,g2as,g2ad,1,ES,ED);
    k_gat<1,1><<<N0,128>>>(S,ES,ED,g2b,Rb,resb,out);
}

// round 6
// speedup vs baseline: 3.6507x; 1.2739x over previous
#include <cuda_runtime.h>
#include <cuda_bf16.h>
#include <math.h>

// ---------------- problem constants ----------------
#define N0 4096
#define N1 2048
#define N2 1024
#define N3 512
#define NE 65536
#define FH 64
#define FO 128
#define MAXD0 128
#define MAXD1 2048

// ---------------- static device scratch ----------------
__device__ unsigned char g_A0b[(size_t)N0*N0];          // byte adjacency counts
__device__ int   g_idx0[(size_t)N0*MAXD0]; __device__ float g_val0[(size_t)N0*MAXD0];
__device__ float g_val0s[(size_t)N0*MAXD0]; __device__ int g_cnt0[N0];
__device__ int   g_idx1[(size_t)N1*MAXD1]; __device__ float g_val1[(size_t)N1*MAXD1];
__device__ float g_val1s[(size_t)N1*MAXD1]; __device__ int g_cnt1[N1];
__device__ float g_A2d[(size_t)N2*N2];
__device__ float g_A2h[(size_t)N2*N2];
__device__ float g_A3d[(size_t)N3*N3];
__device__ float g_A3h[(size_t)N3*N3];
__device__ float g_Rg[(size_t)N3*N2];
__device__ float g_Cg[(size_t)N2*N3];
__device__ float g_Y[(size_t)N0*FO];
__device__ float g_S[(size_t)N0*FO];
__device__ float g_x0[N0*FH], g_x1[N1*FH], g_x2[N2*FH], g_x3[N3*FH];
__device__ float g_hbuf[N0*FH];
__device__ float g_up[N1*FH];
__device__ float g_H[N0*FO];
__device__ float g_U[N0*FO];
__device__ float g_res[N0*FO];
__device__ float g_feat1[(size_t)N0*512];
__device__ float g_gout[(size_t)N0*512];
__device__ float g_dinv0[N0], g_dfix0[N0];
__device__ float g_dinv1[N1], g_dinv2[N2], g_dinv3[N3];
__device__ int   g_perm1[N1]; __device__ float g_vals1[N1];
__device__ int   g_perm2[N2]; __device__ float g_vals2[N2];
__device__ int   g_perm3[N3]; __device__ float g_vals3[N3];
__device__ int   g_ipos1[N0], g_ipos2[N1], g_ipos3[N2];
__device__ float g_es[N0*4], g_ed[N0*4];

// ---------------- SGEMM: exact-divisible fast path, fused epilogue ----------------
// EPI: 0=none, 1=GCN+relu, 2=GCN (v = acc + 2*dinv[r]^2*Yd[r,c] + bias[c])
template<int BM,int BN,int BK,int TM,int TN,int EPI>
__global__ void __launch_bounds__((BM/TM)*(BN/TN))
sgemm2(int M,int N,int K,const float* __restrict__ A,const float* __restrict__ B,
       float* __restrict__ C,const float* __restrict__ Yd,const float* __restrict__ dinv,
       const float* __restrict__ bias){
    constexpr int THREADS=(BM/TM)*(BN/TN);
    __shared__ float As[BK][BM];
    __shared__ float Bs[BK][BN];
    const int bm=blockIdx.y*BM, bn=blockIdx.x*BN;
    const int tid=threadIdx.x;
    const int tcol=tid%(BN/TN), trow=tid/(BN/TN);
    float acc[TM][TN];
    #pragma unroll
    for(int i=0;i<TM;i++)
        #pragma unroll
        for(int j=0;j<TN;j++) acc[i][j]=0.f;

    for(int k0=0;k0<K;k0+=BK){
        for(int i=tid;i<BM*BK/4;i+=THREADS){
            int m=i/(BK/4), kq=i%(BK/4);
            float4 v=*(const float4*)(A+(size_t)(bm+m)*K+k0+kq*4);
            As[kq*4+0][m]=v.x; As[kq*4+1][m]=v.y; As[kq*4+2][m]=v.z; As[kq*4+3][m]=v.w;
        }
        for(int i=tid;i<BK*BN/4;i+=THREADS){
            int k=i/(BN/4), nq=i%(BN/4);
            *(float4*)&Bs[k][nq*4] = *(const float4*)(B+(size_t)(k0+k)*N+bn+nq*4);
        }
        __syncthreads();
        #pragma unroll
        for(int kk=0;kk<BK;kk++){
            float ra[TM], rb[TN];
            #pragma unroll
            for(int i=0;i<TM;i++) ra[i]=As[kk][trow*TM+i];
            #pragma unroll
            for(int j=0;j<TN;j+=4){
                float4 v=*(const float4*)&Bs[kk][tcol*TN+j];
                rb[j]=v.x; rb[j+1]=v.y; rb[j+2]=v.z; rb[j+3]=v.w;
            }
            #pragma unroll
            for(int i=0;i<TM;i++)
                #pragma unroll
                for(int j=0;j<TN;j++) acc[i][j]+=ra[i]*rb[j];
        }
        __syncthreads();
    }
    #pragma unroll
    for(int i=0;i<TM;i++){
        int gm=bm+trow*TM+i;
        float tw = (EPI!=0)? 2.f*dinv[gm]*dinv[gm] : 0.f;
        #pragma unroll
        for(int j=0;j<TN;j++){
            int gn=bn+tcol*TN+j;
            float v=acc[i][j];
            if(EPI!=0){
                v += tw*Yd[(size_t)gm*N+gn] + bias[gn];
                if(EPI==1) v=fmaxf(v,0.f);
            }
            C[(size_t)gm*N+gn]=v;
        }
    }
}

// ---------------- graph build (byte adjacency) ----------------
__global__ void k_buildA0(const int* __restrict__ ei, unsigned int* __restrict__ Aw){
    int e = blockIdx.x*blockDim.x+threadIdx.x;
    if(e<NE){
        int s=ei[e];
        int d=ei[NE+e];
        size_t byteoff=(size_t)d*N0+s;
        atomicAdd(&Aw[byteoff>>2], 1u<<((s&3)*8));
    }
}

// warp per row over packed bytes; non-ascending (4-interleaved) column order is OK
// (all consumers are order-insensitive sums).
__global__ void k_csr0(const unsigned char* __restrict__ Ab,int* __restrict__ idx,float* __restrict__ val,
                       int* __restrict__ cnt,float* __restrict__ dinv,float* __restrict__ dfix){
    int w=(blockIdx.x*blockDim.x+threadIdx.x)>>5;
    int lane=threadIdx.x&31;
    if(w>=N0) return;
    const unsigned int* row=(const unsigned int*)(Ab+(size_t)w*N0);
    int c=0; float rs=0.f;
    for(int base=0;base<N0/4;base+=32){
        unsigned int wv=row[base+lane];
        int colbase=(base+lane)*4;
        #pragma unroll
        for(int b=0;b<4;b++){
            int v=(wv>>(8*b))&255;
            int col=colbase+b;
            bool p=(v!=0)||(col==w);
            unsigned m=__ballot_sync(0xffffffffu,p);
            if(p){
                int off=c+__popc(m&((1u<<lane)-1u));
                idx[(size_t)w*MAXD0+off]=col;
                val[(size_t)w*MAXD0+off]=(float)v;
                rs+=(float)v;
            }
            c+=__popc(m);
        }
    }
    #pragma unroll
    for(int o=16;o;o>>=1) rs+=__shfl_xor_sync(0xffffffffu,rs,o);
    if(lane==0){
        float d=(float)Ab[(size_t)w*N0+w];
        float fx=(d==0.f)?2.f:0.f;
        cnt[w]=c;
        dfix[w]=fx;
        dinv[w]=rsqrtf(rs+fx);
    }
}

__global__ void k_prescale_csr(int n,const int* __restrict__ idx,const float* __restrict__ val,
                               const int* __restrict__ cnt,int maxd,const float* __restrict__ dinv,
                               float* __restrict__ valo){
    int w=(blockIdx.x*blockDim.x+threadIdx.x)>>5;
    int lane=threadIdx.x&31;
    if(w>=n) return;
    float dr=dinv[w];
    int cn=cnt[w];
    for(int e=lane;e<cn;e+=32)
        valo[(size_t)w*maxd+e]=val[(size_t)w*maxd+e]*dr*dinv[idx[(size_t)w*maxd+e]];
}

// ---------------- K=3 input transform ----------------
__global__ void k_xw0(const float* __restrict__ x,const float* __restrict__ w,float* __restrict__ Y){
    __shared__ float sw[3*FH];
    int t=blockIdx.x*blockDim.x+threadIdx.x;
    if(threadIdx.x<3*FH) sw[threadIdx.x]=w[threadIdx.x];
    __syncthreads();
    if(t>=N0*FH) return;
    int r=t/FH, c=t%FH;
    const float* xr=x+(size_t)r*3;
    Y[t]=xr[0]*sw[c]+xr[1]*sw[FH+c]+xr[2]*sw[2*FH+c];
}

// ---------------- CSR SpMM + GCN epilogue ----------------
template<int F>
__global__ void k_spmmf(int n,const int* __restrict__ idx,const float* __restrict__ val,
                        const int* __restrict__ cnt,int maxd,
                        const float* __restrict__ Y,const float* __restrict__ dinv,
                        const float* __restrict__ dfix,const float* __restrict__ b,
                        float* __restrict__ out,int relu){
    int r = blockIdx.x*(256/F) + threadIdx.x/F;
    int c = threadIdx.x%F;
    if(r>=n) return;
    int cn=cnt[r];
    const int* ip=idx+(size_t)r*maxd;
    const float* vp=val+(size_t)r*maxd;
    float acc=0.f;
    for(int e=0;e<cn;e++)
        acc += vp[e]*Y[(size_t)ip[e]*F+c];
    float fx = dfix? dfix[r] : 2.0f;
    float di = dinv[r];
    float v = acc + fx*di*di*Y[(size_t)r*F+c] + b[c];
    out[(size_t)r*F+c] = relu? fmaxf(v,0.f) : v;
}

// ---------------- fused pool: score + bitonic topk + ipos + gather ----------------
template<int N>
__global__ void __launch_bounds__(1024) k_pool(const float* __restrict__ x,const float* __restrict__ p,
                                               int k,int* __restrict__ perm,float* __restrict__ vals,
                                               int* __restrict__ ipos,float* __restrict__ h){
    __shared__ float kk[N];
    __shared__ int   ii[N];
    int t=threadIdx.x;
    float pn=0.f;
    #pragma unroll
    for(int c=0;c<FH;c++){ float pv=p[c]; pn+=pv*pv; }
    float rn=rsqrtf(pn);
    for(int r=t;r<N;r+=1024){
        float d=0.f;
        #pragma unroll
        for(int c=0;c<FH;c++) d+=x[(size_t)r*FH+c]*p[c];
        kk[r]=tanhf(d*rn);
        ii[r]=r;
    }
    __syncthreads();
    for(int size=2;size<=N;size<<=1){
        for(int stride=size>>1;stride>0;stride>>=1){
            for(int i=t;i<(N>>1);i+=1024){
                int lo = 2*i - (i&(stride-1));
                int hi = lo+stride;
                bool up = ((lo & size)==0);
                float ka=kk[lo], kb=kk[hi];
                int ia=ii[lo], ib=ii[hi];
                bool beforeBA = (kb>ka) || (kb==ka && ib<ia);
                bool sw = up ? beforeBA : !beforeBA;
                if(sw){ kk[lo]=kb;kk[hi]=ka;ii[lo]=ib;ii[hi]=ia; }
            }
            __syncthreads();
        }
    }
    for(int i=t;i<N;i+=1024) ipos[ii[i]] = (i<k)? i : -1;
    for(int i=t;i<k;i+=1024){ perm[i]=ii[i]; vals[i]=kk[i]; }
    for(int idx=t;idx<k*FH;idx+=1024){
        int i=idx/FH, c=idx%FH;
        h[idx]=x[(size_t)ii[i]*FH+c]*kk[i];
    }
}

// ---------------- SpGEMM level1 (CSR out, input HAS diag entries) ----------------
template<int NCOL>
__global__ void __launch_bounds__(256) k_spgemm_csr(
        const int* __restrict__ inIdx,const float* __restrict__ inVal,const int* __restrict__ inCnt,int inMaxd,
        const int* __restrict__ perm,const int* __restrict__ ipos,
        int* __restrict__ outIdx,float* __restrict__ outVal,int* __restrict__ outCnt,int outMaxd,
        float* __restrict__ dinv){
    __shared__ float acc[NCOL];
    int i=blockIdx.x, t=threadIdx.x;
    for(int j=t;j<NCOL;j+=256) acc[j]=0.f;
    __syncthreads();
    int r0=perm[i];
    int cr=inCnt[r0];
    const int* rip=inIdx+(size_t)r0*inMaxd;
    const float* rvp=inVal+(size_t)r0*inMaxd;
    int warp=t>>5, lane=t&31;
    for(int e=warp;e<cr;e+=8){
        int k=rip[e];
        float rv=rvp[e] + ((k==r0)?1.f:0.f);
        int ck=inCnt[k];
        const int* kip=inIdx+(size_t)k*inMaxd;
        const float* kvp=inVal+(size_t)k*inMaxd;
        for(int f=lane;f<ck;f+=32){
            int s=kip[f];
            float cv=kvp[f] + ((s==k)?1.f:0.f);
            int j=ipos[s];
            if(j>=0) atomicAdd(&acc[j], rv*cv);
        }
    }
    __syncthreads();
    if(t==0) acc[i]=0.f;
    __syncthreads();
    if(warp==0){
        int c=0; float rs=0.f;
        for(int base=0;base<NCOL;base+=32){
            int j=base+lane;
            float v=acc[j];
            bool p=(v!=0.f);
            unsigned m=__ballot_sync(0xffffffffu,p);
            if(p){
                int off=c+__popc(m&((1u<<lane)-1u));
                outIdx[(size_t)i*outMaxd+off]=j;
                outVal[(size_t)i*outMaxd+off]=v;
                rs+=v;
            }
            c+=__popc(m);
        }
        #pragma unroll
        for(int o=16;o;o>>=1) rs+=__shfl_xor_sync(0xffffffffu,rs,o);
        if(lane==0){ outCnt[i]=c; dinv[i]=rsqrtf(rs+2.f); }
    }
}

// ---------------- SpGEMM level2 (dense out, input CSR has NO diag) ----------------
template<int NCOL>
__global__ void __launch_bounds__(256) k_spgemm_dense(
        const int* __restrict__ inIdx,const float* __restrict__ inVal,const int* __restrict__ inCnt,int inMaxd,
        const int* __restrict__ perm,const int* __restrict__ ipos,
        float* __restrict__ outD,float* __restrict__ dinv){
    __shared__ float acc[NCOL];
    __shared__ float red[8];
    int i=blockIdx.x, t=threadIdx.x;
    for(int j=t;j<NCOL;j+=256) acc[j]=0.f;
    __syncthreads();
    int r0=perm[i];
    int cr=inCnt[r0];
    int total=cr+1;
    const int* rip=inIdx+(size_t)r0*inMaxd;
    const float* rvp=inVal+(size_t)r0*inMaxd;
    int warp=t>>5, lane=t&31;
    for(int e=warp;e<total;e+=8){
        int k; float rv;
        if(e<cr){ k=rip[e]; rv=rvp[e]; }
        else    { k=r0; rv=1.f; }
        int ck=inCnt[k];
        const int* kip=inIdx+(size_t)k*inMaxd;
        const float* kvp=inVal+(size_t)k*inMaxd;
        int tot2=ck+1;
        for(int f=lane;f<tot2;f+=32){
            int s; float cv;
            if(f<ck){ s=kip[f]; cv=kvp[f]; }
            else    { s=k; cv=1.f; }
            int j=ipos[s];
            if(j>=0) atomicAdd(&acc[j], rv*cv);
        }
    }
    __syncthreads();
    if(t==0) acc[i]=0.f;
    __syncthreads();
    float rs=0.f;
    for(int j=t;j<NCOL;j+=256){ rs+=acc[j]; outD[(size_t)i*NCOL+j]=acc[j]; }
    #pragma unroll
    for(int o=16;o;o>>=1) rs+=__shfl_xor_sync(0xffffffffu,rs,o);
    if(lane==0) red[warp]=rs;
    __syncthreads();
    if(t==0){
        float s=0.f;
        #pragma unroll
        for(int w=0;w<8;w++) s+=red[w];
        dinv[i]=rsqrtf(s+2.f);
    }
}

// ---------------- level-3 dense helpers ----------------
__global__ void k_gatherR(const float* __restrict__ A,int n,const int* __restrict__ perm,int m,float* __restrict__ R){
    size_t t=(size_t)blockIdx.x*blockDim.x+threadIdx.x;
    if(t>=(size_t)m*n) return;
    int i=(int)(t/n), k=(int)(t%n);
    int pi=perm[i];
    R[t]=A[(size_t)pi*n+k] + ((k==pi)?1.f:0.f);
}
__global__ void k_gatherC(const float* __restrict__ A,int n,const int* __restrict__ perm,int m,float* __restrict__ C){
    size_t t=(size_t)blockIdx.x*blockDim.x+threadIdx.x;
    if(t>=(size_t)m*n) return;
    int k=(int)(t/m), j=(int)(t%m);
    int pj=perm[j];
    C[t]=A[(size_t)k*n+pj] + ((k==pj)?1.f:0.f);
}
__global__ void __launch_bounds__(256) k_finishA3(float* __restrict__ A,int m,float* __restrict__ dinv){
    __shared__ float red[8];
    int r=blockIdx.x, t=threadIdx.x;
    if(t==0) A[(size_t)r*m+r]=0.f;
    __syncthreads();
    float s=0.f;
    for(int j=t;j<m;j+=256) s+=A[(size_t)r*m+j];
    #pragma unroll
    for(int o=16;o;o>>=1) s+=__shfl_xor_sync(0xffffffffu,s,o);
    if((t&31)==0) red[t>>5]=s;
    __syncthreads();
    if(t==0){
        float ss=0.f;
        #pragma unroll
        for(int w=0;w<8;w++) ss+=red[w];
        dinv[r]=rsqrtf(ss+2.f);
    }
}
__global__ void k_prescale_dense(const float* __restrict__ A,int m,const float* __restrict__ dinv,float* __restrict__ O){
    size_t t=(size_t)blockIdx.x*blockDim.x+threadIdx.x;
    if(t>=(size_t)m*m) return;
    int r=(int)(t/m), c=(int)(t%m);
    O[t]=A[t]*dinv[r]*dinv[c];
}

// up-merge: h = x_fine + scatter(xs at perm) via inverse perm
__global__ void k_upmerge(const float* __restrict__ xf,const int* __restrict__ ipos,
                          const float* __restrict__ xs,float* __restrict__ h,int tot){
    int t=blockIdx.x*blockDim.x+threadIdx.x;
    if(t>=tot) return;
    int r=t/FH;
    int j=ipos[r];
    float v=xf[t];
    if(j>=0) v+=xs[(size_t)j*FH + (t%FH)];
    h[t]=v;
}

// ---------------- layernorm ----------------
__global__ void k_ln(const float* __restrict__ h,const float* __restrict__ g,const float* __restrict__ b,float* __restrict__ u){
    __shared__ float red[128];
    int i=blockIdx.x, t=threadIdx.x;
    float v=h[(size_t)i*FO+t];
    red[t]=v; __syncthreads();
    for(int o=64;o;o>>=1){ if(t<o) red[t]+=red[t+o]; __syncthreads(); }
    float mu=red[0]/FO; __syncthreads();
    float d=v-mu;
    red[t]=d*d; __syncthreads();
    for(int o=64;o;o>>=1){ if(t<o) red[t]+=red[t+o]; __syncthreads(); }
    float var=red[0]/FO;
    u[(size_t)i*FO+t]=d*rsqrtf(var+1e-6f)*g[t]+b[t];
}

// ---------------- GAT ----------------
__global__ void k_esed(const float* __restrict__ feat,const float* __restrict__ asrc,const float* __restrict__ adst,int heads,float* __restrict__ es,float* __restrict__ ed){
    int w=(blockIdx.x*blockDim.x+threadIdx.x)>>5;
    int lane=threadIdx.x&31;
    if(w>=N0) return;
    for(int h=0;h<heads;h++){
        float a=0.f,d=0.f;
        for(int c=lane;c<FO;c+=32){
            float f=feat[(size_t)w*(heads*FO)+h*FO+c];
            a+=f*asrc[h*FO+c];
            d+=f*adst[h*FO+c];
        }
        #pragma unroll
        for(int o=16;o;o>>=1){ a+=__shfl_xor_sync(0xffffffffu,a,o); d+=__shfl_xor_sync(0xffffffffu,d,o); }
        if(lane==0){ es[w*heads+h]=a; ed[w*heads+h]=d; }
    }
}

// MODE 0: out = elu(acc + bias).  MODE 1: out = acc + bias + res + resb (final).
template<int HEADS,int MODE>
__global__ void __launch_bounds__(128) k_gat(const float* __restrict__ feat,const float* __restrict__ es,const float* __restrict__ ed,
                                             const float* __restrict__ bias,const float* __restrict__ res,const float* __restrict__ resb,
                                             float* __restrict__ out){
    __shared__ int snbr[MAXD0];
    __shared__ float salpha[MAXD0*HEADS];
    __shared__ float smax[HEADS], sinv[HEADS];
    int d=blockIdx.x, t=threadIdx.x;
    int cnt=g_cnt0[d];
    for(int i=t;i<cnt;i+=128) snbr[i]=g_idx0[(size_t)d*MAXD0+i];
    __syncthreads();
    for(int i=t;i<cnt;i+=128){
        int s=snbr[i];
        #pragma unroll
        for(int h=0;h<HEADS;h++){
            float l=ed[d*HEADS+h]+es[s*HEADS+h];
            l = (l>0.f)? l : 0.2f*l;
            salpha[i*HEADS+h]=l;
        }
    }
    __syncthreads();
    if(t<HEADS){
        float mx=-1e30f;
        for(int i=0;i<cnt;i++) mx=fmaxf(mx,salpha[i*HEADS+t]);
        float sm=0.f;
        for(int i=0;i<cnt;i++) sm+=expf(salpha[i*HEADS+t]-mx);
        smax[t]=mx; sinv[t]=1.f/sm;
    }
    __syncthreads();
    for(int i=t;i<cnt*HEADS;i+=128){
        int h=i%HEADS;
        salpha[i]=expf(salpha[i]-smax[h])*sinv[h];
    }
    __syncthreads();
    #pragma unroll
    for(int h=0;h<HEADS;h++){
        float acc=0.f;
        for(int i=0;i<cnt;i++)
            acc += salpha[i*HEADS+h]*feat[(size_t)snbr[i]*(HEADS*FO)+h*FO+t];
        if(MODE==0){
            float v=acc+bias[h*FO+t];
            out[(size_t)d*(HEADS*FO)+h*FO+t]= (v>0.f)? v : expm1f(v);
        } else {
            out[(size_t)d*FO+t]=acc+bias[t]+res[(size_t)d*FO+t]+resb[t];
        }
    }
}

// ---------------- host ----------------
static inline int cdiv(int a,int b){return (a+b-1)/b;}

template<typename T> static T* symaddr(const void* sym){
    void* p=nullptr;
    cudaGetSymbolAddress(&p, sym);
    return (T*)p;
}

// all shapes divide tiles exactly
static void gemm16(int M,int N,int K,const float*A,const float*B,float*C){
    dim3 g(N/64, M/16);
    sgemm2<16,64,16,1,4,0><<<g,256>>>(M,N,K,A,B,C,nullptr,nullptr,nullptr);
}
static void gemm16_gcn(int M,int N,int K,const float*A,const float*B,float*C,
                       const float*Yd,const float*di,const float*b,bool relu){
    dim3 g(N/64, M/16);
    if(relu) sgemm2<16,64,16,1,4,1><<<g,256>>>(M,N,K,A,B,C,Yd,di,b);
    else     sgemm2<16,64,16,1,4,2><<<g,256>>>(M,N,K,A,B,C,Yd,di,b);
}
static void gemm64(int M,int N,int K,const float*A,const float*B,float*C){
    dim3 g(N/64, M/64);
    sgemm2<64,64,16,4,4,0><<<g,256>>>(M,N,K,A,B,C,nullptr,nullptr,nullptr);
}

extern "C" void kernel_launch(void* const* d_in, const int* in_sizes, int n_in,
                              void* d_out, int out_size) {
    const float* x      =(const float*)d_in[0];
    const int*   ei     =(const int*  )d_in[1];
    const float* w0=(const float*)d_in[2],  *b0=(const float*)d_in[3];
    const float* w1=(const float*)d_in[4],  *b1=(const float*)d_in[5];
    const float* w2=(const float*)d_in[6],  *b2=(const float*)d_in[7];
    const float* w3=(const float*)d_in[8],  *b3=(const float*)d_in[9];
    const float* p1=(const float*)d_in[10], *p2=(const float*)d_in[11], *p3=(const float*)d_in[12];
    const float* uw0=(const float*)d_in[13],*ub0=(const float*)d_in[14];
    const float* uw1=(const float*)d_in[15],*ub1=(const float*)d_in[16];
    const float* uw2=(const float*)d_in[17],*ub2=(const float*)d_in[18];
    const float* lng=(const float*)d_in[19],*lnb=(const float*)d_in[20];
    const float* resw=(const float*)d_in[21],*resb=(const float*)d_in[22];
    const float* g1w=(const float*)d_in[23],*g1as=(const float*)d_in[24],*g1ad=(const float*)d_in[25],*g1b=(const float*)d_in[26];
    const float* g2w=(const float*)d_in[27],*g2as=(const float*)d_in[28],*g2ad=(const float*)d_in[29],*g2b=(const float*)d_in[30];

    unsigned char* A0b=symaddr<unsigned char>(g_A0b);
    int* idx0=symaddr<int>(g_idx0); float* val0=symaddr<float>(g_val0);
    float* val0s=symaddr<float>(g_val0s); int* cnt0=symaddr<int>(g_cnt0);
    int* idx1=symaddr<int>(g_idx1); float* val1=symaddr<float>(g_val1);
    float* val1s=symaddr<float>(g_val1s); int* cnt1=symaddr<int>(g_cnt1);
    float* A2d=symaddr<float>(g_A2d); float* A2h=symaddr<float>(g_A2h);
    float* A3d=symaddr<float>(g_A3d); float* A3h=symaddr<float>(g_A3h);
    float* Rg=symaddr<float>(g_Rg); float* Cg=symaddr<float>(g_Cg);
    float* Y=symaddr<float>(g_Y);   float* S=symaddr<float>(g_S);
    float* x0b=symaddr<float>(g_x0);float* x1b=symaddr<float>(g_x1);
    float* x2b=symaddr<float>(g_x2);float* x3b=symaddr<float>(g_x3);
    float* hb=symaddr<float>(g_hbuf); float* upb=symaddr<float>(g_up);
    float* Hb=symaddr<float>(g_H);  float* Ub=symaddr<float>(g_U);  float* Rb=symaddr<float>(g_res);
    float* F1=symaddr<float>(g_feat1); float* GO=symaddr<float>(g_gout);
    float* di0=symaddr<float>(g_dinv0); float* df0=symaddr<float>(g_dfix0);
    float* di1=symaddr<float>(g_dinv1); float* di2=symaddr<float>(g_dinv2); float* di3=symaddr<float>(g_dinv3);
    int* pm1=symaddr<int>(g_perm1); float* vl1=symaddr<float>(g_vals1);
    int* pm2=symaddr<int>(g_perm2); float* vl2=symaddr<float>(g_vals2);
    int* pm3=symaddr<int>(g_perm3); float* vl3=symaddr<float>(g_vals3);
    int* ip1=symaddr<int>(g_ipos1); int* ip2=symaddr<int>(g_ipos2); int* ip3=symaddr<int>(g_ipos3);
    float* ES=symaddr<float>(g_es); float* ED=symaddr<float>(g_ed);
    float* out=(float*)d_out;

    // ---- build A0 (bytes) + CSR0 + prescale ----
    cudaMemsetAsync(A0b,0,(size_t)N0*N0,0);
    k_buildA0<<<cdiv(NE,256),256>>>(ei,(unsigned int*)A0b);
    k_csr0<<<cdiv(N0,8),256>>>(A0b,idx0,val0,cnt0,di0,df0);
    k_prescale_csr<<<cdiv(N0,8),256>>>(N0,idx0,val0,cnt0,MAXD0,di0,val0s);

    // ---- gcn0 down ----
    k_xw0<<<cdiv(N0*FH,256),256>>>(x,w0,Y);
    k_spmmf<64><<<cdiv(N0*64,256),256>>>(N0,idx0,val0s,cnt0,MAXD0,Y,di0,df0,b0,x0b,1);

    // ---- pool1 + A1 (sparse) ----
    k_pool<N0><<<1,1024>>>(x0b,p1,N1,pm1,vl1,ip1,hb);
    k_spgemm_csr<N1><<<N1,256>>>(idx0,val0,cnt0,MAXD0,pm1,ip1,idx1,val1,cnt1,MAXD1,di1);
    k_prescale_csr<<<cdiv(N1,8),256>>>(N1,idx1,val1,cnt1,MAXD1,di1,val1s);

    // ---- gcn1 down ----
    gemm16(N1,FH,FH,hb,w1,Y);
    k_spmmf<64><<<cdiv(N1*64,256),256>>>(N1,idx1,val1s,cnt1,MAXD1,Y,di1,nullptr,b1,x1b,1);

    // ---- pool2 + A2 (dense out) ----
    k_pool<N1><<<1,1024>>>(x1b,p2,N2,pm2,vl2,ip2,hb);
    k_spgemm_dense<N2><<<N2,256>>>(idx1,val1,cnt1,MAXD1,pm2,ip2,A2d,di2);
    k_prescale_dense<<<cdiv(N2*N2,256),256>>>(A2d,N2,di2,A2h);

    // ---- gcn2 down (dense, fused epilogue) ----
    gemm16(N2,FH,FH,hb,w2,Y);
    gemm16_gcn(N2,FH,N2,A2h,Y,x2b, Y,di2,b2,true);

    // ---- pool3 + A3 (dense GEMM) ----
    k_pool<N2><<<1,1024>>>(x2b,p3,N3,pm3,vl3,ip3,hb);
    k_gatherR<<<cdiv(N3*N2,256),256>>>(A2d,N2,pm3,N3,Rg);
    k_gatherC<<<cdiv(N3*N2,256),256>>>(A2d,N2,pm3,N3,Cg);
    gemm16(N3,N3,N2,Rg,Cg,A3d);
    k_finishA3<<<N3,256>>>(A3d,N3,di3);
    k_prescale_dense<<<cdiv(N3*N3,256),256>>>(A3d,N3,di3,A3h);

    // ---- gcn3 down ----
    gemm16(N3,FH,FH,hb,w3,Y);
    gemm16_gcn(N3,FH,N3,A3h,Y,x3b, Y,di3,b3,true);

    // ---- up path ----
    k_upmerge<<<cdiv(N2*FH,256),256>>>(x2b,ip3,x3b,hb,N2*FH);
    gemm16(N2,FH,FH,hb,uw0,Y);
    gemm16_gcn(N2,FH,N2,A2h,Y,upb, Y,di2,ub0,true);

    k_upmerge<<<cdiv(N1*FH,256),256>>>(x1b,ip2,upb,hb,N1*FH);
    gemm16(N1,FH,FH,hb,uw1,Y);
    k_spmmf<64><<<cdiv(N1*64,256),256>>>(N1,idx1,val1s,cnt1,MAXD1,Y,di1,nullptr,ub1,upb,1);

    k_upmerge<<<cdiv(N0*FH,256),256>>>(x0b,ip1,upb,hb,N0*FH);
    gemm16(N0,FO,FH,hb,uw2,Y);
    k_spmmf<128><<<cdiv(N0*128,256),256>>>(N0,idx0,val0s,cnt0,MAXD0,Y,di0,df0,ub2,Hb,0);

    // ---- layernorm + residual ----
    k_ln<<<N0,128>>>(Hb,lng,lnb,Ub);
    gemm16(N0,FO,FO,Ub,resw,Rb);

    // ---- GAT layers ----
    gemm64(N0,4*FO,FO,Ub,g1w,F1);
    k_esed<<<cdiv(N0,8),256>>>(F1,g1as,g1ad,4,ES,ED);
    k_gat<4,0><<<N0,128>>>(F1,ES,ED,g1b,nullptr,nullptr,GO);

    gemm16(N0,FO,4*FO,GO,g2w,S);
    k_esed<<<cdiv(N0,8),256>>>(S,g2as,g2ad,1,ES,ED);
    k_gat<1,1><<<N0,128>>>(S,ES,ED,g2b,Rb,resb,out);
}

// round 8
// speedup vs baseline: 4.6829x; 1.2828x over previous
#include <cuda_runtime.h>
#include <cuda_bf16.h>
#include <math.h>

// ---------------- problem constants ----------------
#define N0 4096
#define N1 2048
#define N2 1024
#define N3 512
#define NE 65536
#define FH 64
#define FO 128
#define MAXD0 128
#define MAXD1 2048

// ---------------- static device scratch ----------------
__device__ unsigned char g_A0b[(size_t)N0*N0];
__device__ int   g_idx0[(size_t)N0*MAXD0]; __device__ float g_val0[(size_t)N0*MAXD0];
__device__ float g_val0s[(size_t)N0*MAXD0]; __device__ int g_cnt0[N0];
__device__ int   g_idx1[(size_t)N1*MAXD1]; __device__ float g_val1[(size_t)N1*MAXD1];
__device__ float g_val1s[(size_t)N1*MAXD1]; __device__ int g_cnt1[N1];
__device__ float g_A2d[(size_t)N2*N2];
__device__ float g_A3d[(size_t)N3*N3];
__device__ float g_Rg[(size_t)N3*N2];
__device__ float g_Cg[(size_t)N2*N3];
__device__ float g_part[1<<20];          // split-K partials (4MB)
__device__ float g_Y[(size_t)N0*FO];
__device__ float g_S[(size_t)N0*FO];
__device__ float g_x0[N0*FH], g_x1[N1*FH], g_x2[N2*FH], g_x3[N3*FH];
__device__ float g_hbuf[N0*FH];
__device__ float g_up[N1*FH];
__device__ float g_U[N0*FO];
__device__ float g_res[N0*FO];
__device__ float g_feat1[(size_t)N0*512];
__device__ float g_gout[(size_t)N0*512];
__device__ float g_dinv0[N0], g_dfix0[N0];
__device__ float g_dinv1[N1], g_dinv2[N2], g_dinv3[N3];
__device__ int   g_perm1[N1]; __device__ float g_vals1[N1];
__device__ int   g_perm2[N2]; __device__ float g_vals2[N2];
__device__ int   g_perm3[N3]; __device__ float g_vals3[N3];
__device__ int   g_ipos1[N0], g_ipos2[N1], g_ipos3[N2];
__device__ float g_es[N0*4], g_ed[N0*4];

static inline int cdiv(int a,int b){return (a+b-1)/b;}

// ---------------- gemmBig: 64x64x16, TM=TN=4, 256 threads, optional split-K ----------------
__global__ void __launch_bounds__(256)
gemmBig(int M,int N,int K,int KS,const float* __restrict__ A,const float* __restrict__ B,
        float* __restrict__ dest){
    __shared__ __align__(16) float As[16][64];
    __shared__ __align__(16) float Bs[16][64];
    const int bm=blockIdx.y*64, bn=blockIdx.x*64, z=blockIdx.z;
    const int tid=threadIdx.x;
    const int trow=tid/16, tcol=tid%16;
    const int kchunk=K/KS;
    const int kbeg=z*kchunk, kend=kbeg+kchunk;
    float acc[4][4];
    #pragma unroll
    for(int i=0;i<4;i++)
        #pragma unroll
        for(int j=0;j<4;j++) acc[i][j]=0.f;

    for(int k0=kbeg;k0<kend;k0+=16){
        {
            int m=tid/4, kq=tid%4;
            float4 v=*(const float4*)(A+(size_t)(bm+m)*K+k0+kq*4);
            As[kq*4+0][m]=v.x; As[kq*4+1][m]=v.y; As[kq*4+2][m]=v.z; As[kq*4+3][m]=v.w;
        }
        {
            int k=tid/16, nq=tid%16;
            *(float4*)&Bs[k][nq*4] = *(const float4*)(B+(size_t)(k0+k)*N+bn+nq*4);
        }
        __syncthreads();
        #pragma unroll
        for(int kk=0;kk<16;kk++){
            float4 ra=*(const float4*)&As[kk][trow*4];
            float4 rb=*(const float4*)&Bs[kk][tcol*4];
            float a[4]={ra.x,ra.y,ra.z,ra.w};
            float b[4]={rb.x,rb.y,rb.z,rb.w};
            #pragma unroll
            for(int i=0;i<4;i++)
                #pragma unroll
                for(int j=0;j<4;j++) acc[i][j]+=a[i]*b[j];
        }
        __syncthreads();
    }
    float* out=dest+(size_t)z*M*N;
    #pragma unroll
    for(int i=0;i<4;i++){
        int gm=bm+trow*4+i;
        #pragma unroll
        for(int j=0;j<4;j++){
            out[(size_t)gm*N+bn+tcol*4+j]=acc[i][j];
        }
    }
}

// split-K reduce + GCN epilogue: v = di[r]*sum + 2*di[r]*Ys[t] + b[c]; optional relu
__global__ void k_kred_gcn(int n,int f,int KS,const float* __restrict__ part,
                           const float* __restrict__ Ys,const float* __restrict__ di,
                           const float* __restrict__ b,float* __restrict__ out,int relu){
    int t=blockIdx.x*blockDim.x+threadIdx.x;
    if(t>=n*f) return;
    float acc=0.f;
    for(int z=0;z<KS;z++) acc+=part[(size_t)z*n*f+t];
    int r=t/f;
    float d=di[r];
    float v=d*acc + 2.f*d*Ys[t] + b[t%f];
    out[t]= relu? fmaxf(v,0.f) : v;
}

// A3 split-K reduce (KS=4) + zero diag + rowsum -> dinv3
__global__ void __launch_bounds__(256) k_finishA3red(const float* __restrict__ part,
                                                     float* __restrict__ A3,float* __restrict__ dinv){
    __shared__ float red[8];
    int r=blockIdx.x, t=threadIdx.x;
    float s=0.f;
    for(int j=t;j<N3;j+=256){
        float acc=part[(size_t)0*N3*N3 + r*N3 + j]
                 +part[(size_t)1*N3*N3 + r*N3 + j]
                 +part[(size_t)2*N3*N3 + r*N3 + j]
                 +part[(size_t)3*N3*N3 + r*N3 + j];
        if(j==r) acc=0.f;
        A3[(size_t)r*N3+j]=acc;
        s+=acc;
    }
    #pragma unroll
    for(int o=16;o;o>>=1) s+=__shfl_xor_sync(0xffffffffu,s,o);
    if((t&31)==0) red[t>>5]=s;
    __syncthreads();
    if(t==0){
        float ss=0.f;
        #pragma unroll
        for(int w=0;w<8;w++) ss+=red[w];
        dinv[r]=rsqrtf(ss+2.f);
    }
}

// ---------------- gemm16: 16x64x16, TM=1,TN=4, 256 threads ----------------
// EPI 0: plain. EPI 3: C = di[r]*acc.  MERGE: A += scatter(xs at ipos)
template<int EPI,int MERGE>
__global__ void __launch_bounds__(256)
gemm16(int M,int N,int K,const float* __restrict__ Af,const float* __restrict__ B,
       float* __restrict__ C,const float* __restrict__ di,
       const int* __restrict__ ipos,const float* __restrict__ xs){
    __shared__ __align__(16) float As[16][16];
    __shared__ __align__(16) float Bs[16][64];
    const int bm=blockIdx.y*16, bn=blockIdx.x*64;
    const int tid=threadIdx.x;
    const int trow=tid/16, tcol=tid%16;
    float acc[4]={0.f,0.f,0.f,0.f};
    for(int k0=0;k0<K;k0+=16){
        {
            int m=tid/16, k=tid%16;
            int gm=bm+m, gk=k0+k;
            float a=Af[(size_t)gm*K+gk];
            if(MERGE){ int j=ipos[gm]; if(j>=0) a+=xs[(size_t)j*K+gk]; }
            As[k][m]=a;
        }
        {
            int k=tid/16, nq=tid%16;
            *(float4*)&Bs[k][nq*4] = *(const float4*)(B+(size_t)(k0+k)*N+bn+nq*4);
        }
        __syncthreads();
        #pragma unroll
        for(int kk=0;kk<16;kk++){
            float a=As[kk][trow];
            float4 rb=*(const float4*)&Bs[kk][tcol*4];
            acc[0]+=a*rb.x; acc[1]+=a*rb.y; acc[2]+=a*rb.z; acc[3]+=a*rb.w;
        }
        __syncthreads();
    }
    int gm=bm+trow;
    float scale=(EPI==3)? di[gm] : 1.f;
    #pragma unroll
    for(int j=0;j<4;j++)
        C[(size_t)gm*N+bn+tcol*4+j]=acc[j]*scale;
}

// ---------------- graph build ----------------
__global__ void k_buildA0(const int* __restrict__ ei, unsigned int* __restrict__ Aw){
    int e = blockIdx.x*blockDim.x+threadIdx.x;
    if(e<NE){
        int s=ei[e];
        int d=ei[NE+e];
        size_t byteoff=(size_t)d*N0+s;
        atomicAdd(&Aw[byteoff>>2], 1u<<((s&3)*8));
    }
}

__global__ void k_csr0(const unsigned char* __restrict__ Ab,int* __restrict__ idx,float* __restrict__ val,
                       int* __restrict__ cnt,float* __restrict__ dinv,float* __restrict__ dfix){
    int w=(blockIdx.x*blockDim.x+threadIdx.x)>>5;
    int lane=threadIdx.x&31;
    if(w>=N0) return;
    const unsigned int* row=(const unsigned int*)(Ab+(size_t)w*N0);
    int c=0; float rs=0.f;
    for(int base=0;base<N0/4;base+=32){
        unsigned int wv=row[base+lane];
        int colbase=(base+lane)*4;
        #pragma unroll
        for(int b=0;b<4;b++){
            int v=(wv>>(8*b))&255;
            int col=colbase+b;
            bool p=(v!=0)||(col==w);
            unsigned m=__ballot_sync(0xffffffffu,p);
            if(p){
                int off=c+__popc(m&((1u<<lane)-1u));
                idx[(size_t)w*MAXD0+off]=col;
                val[(size_t)w*MAXD0+off]=(float)v;
                rs+=(float)v;
            }
            c+=__popc(m);
        }
    }
    #pragma unroll
    for(int o=16;o;o>>=1) rs+=__shfl_xor_sync(0xffffffffu,rs,o);
    if(lane==0){
        float d=(float)Ab[(size_t)w*N0+w];
        float fx=(d==0.f)?2.f:0.f;
        cnt[w]=c;
        dfix[w]=fx;
        dinv[w]=rsqrtf(rs+fx);
    }
}

__global__ void k_prescale_csr(int n,const int* __restrict__ idx,const float* __restrict__ val,
                               const int* __restrict__ cnt,int maxd,const float* __restrict__ dinv,
                               float* __restrict__ valo){
    int w=(blockIdx.x*blockDim.x+threadIdx.x)>>5;
    int lane=threadIdx.x&31;
    if(w>=n) return;
    float dr=dinv[w];
    int cn=cnt[w];
    for(int e=lane;e<cn;e+=32)
        valo[(size_t)w*maxd+e]=val[(size_t)w*maxd+e]*dr*dinv[idx[(size_t)w*maxd+e]];
}

// ---------------- K=3 input transform ----------------
__global__ void k_xw0(const float* __restrict__ x,const float* __restrict__ w,float* __restrict__ Y){
    __shared__ float sw[3*FH];
    int t=blockIdx.x*blockDim.x+threadIdx.x;
    if(threadIdx.x<3*FH) sw[threadIdx.x]=w[threadIdx.x];
    __syncthreads();
    if(t>=N0*FH) return;
    int r=t/FH, c=t%FH;
    const float* xr=x+(size_t)r*3;
    Y[t]=xr[0]*sw[c]+xr[1]*sw[FH+c]+xr[2]*sw[2*FH+c];
}

// ---------------- CSR SpMM + GCN epilogue ----------------
template<int F>
__global__ void k_spmmf(int n,const int* __restrict__ idx,const float* __restrict__ val,
                        const int* __restrict__ cnt,int maxd,
                        const float* __restrict__ Y,const float* __restrict__ dinv,
                        const float* __restrict__ dfix,const float* __restrict__ b,
                        float* __restrict__ out,int relu){
    int r = blockIdx.x*(256/F) + threadIdx.x/F;
    int c = threadIdx.x%F;
    if(r>=n) return;
    int cn=cnt[r];
    const int* ip=idx+(size_t)r*maxd;
    const float* vp=val+(size_t)r*maxd;
    float acc=0.f;
    for(int e=0;e<cn;e++)
        acc += vp[e]*Y[(size_t)ip[e]*F+c];
    float fx = dfix? dfix[r] : 2.0f;
    float di = dinv[r];
    float v = acc + fx*di*di*Y[(size_t)r*F+c] + b[c];
    out[(size_t)r*F+c] = relu? fmaxf(v,0.f) : v;
}

// CSR SpMM (F=128) + LayerNorm fused (2 rows per 256-thread block)
__global__ void __launch_bounds__(256) k_spmmLN(const int* __restrict__ idx,const float* __restrict__ val,
                        const int* __restrict__ cnt,
                        const float* __restrict__ Y,const float* __restrict__ dinv,
                        const float* __restrict__ dfix,const float* __restrict__ b,
                        const float* __restrict__ lg,const float* __restrict__ lb,
                        float* __restrict__ u){
    __shared__ float sh[256];
    int r = blockIdx.x*2 + threadIdx.x/128;
    int c = threadIdx.x%128;
    int base = threadIdx.x & 128;
    int cn=cnt[r];
    const int* ip=idx+(size_t)r*MAXD0;
    const float* vp=val+(size_t)r*MAXD0;
    float acc=0.f;
    for(int e=0;e<cn;e++)
        acc += vp[e]*Y[(size_t)ip[e]*FO+c];
    float di=dinv[r];
    float v = acc + dfix[r]*di*di*Y[(size_t)r*FO+c] + b[c];
    sh[threadIdx.x]=v; __syncthreads();
    for(int o=64;o;o>>=1){ if(c<o) sh[base+c]+=sh[base+c+o]; __syncthreads(); }
    float mu=sh[base]/128.f; __syncthreads();
    float d=v-mu;
    sh[threadIdx.x]=d*d; __syncthreads();
    for(int o=64;o;o>>=1){ if(c<o) sh[base+c]+=sh[base+c+o]; __syncthreads(); }
    float var=sh[base]/128.f;
    u[(size_t)r*FO+c]=d*rsqrtf(var+1e-6f)*lg[c]+lb[c];
}

// ---------------- fused pool: score + packed bitonic topk + ipos + gather ----------------
template<int N>
__global__ void __launch_bounds__(1024) k_pool(const float* __restrict__ x,const float* __restrict__ p,
                                               int k,int* __restrict__ perm,float* __restrict__ vals,
                                               int* __restrict__ ipos,float* __restrict__ h){
    __shared__ unsigned long long P[N];
    __shared__ float sk[2048];   // top-k keys (k <= 2048 always)
    int t=threadIdx.x;
    float pn=0.f;
    #pragma unroll
    for(int c=0;c<FH;c++){ float pv=p[c]; pn+=pv*pv; }
    float rn=rsqrtf(pn);
    for(int r=t;r<N;r+=1024){
        float d=0.f;
        #pragma unroll
        for(int c=0;c<FH;c++) d+=x[(size_t)r*FH+c]*p[c];
        float key=tanhf(d*rn);
        unsigned int f=__float_as_uint(key);
        unsigned int u=f ^ ((f&0x80000000u)? 0xFFFFFFFFu : 0x80000000u);
        P[r]=((unsigned long long)u<<32) | (unsigned int)(0xFFFFFFFFu - r);
    }
    __syncthreads();
    for(int size=2;size<=N;size<<=1){
        for(int stride=size>>1;stride>0;stride>>=1){
            for(int i=t;i<(N>>1);i+=1024){
                int lo = 2*i - (i&(stride-1));
                int hi = lo+stride;
                bool up = ((lo & size)==0);
                unsigned long long a=P[lo], b=P[hi];
                bool sw = up ? (b>a) : (a>b);
                if(sw){ P[lo]=b; P[hi]=a; }
            }
            __syncthreads();
        }
    }
    for(int i=t;i<N;i+=1024){
        unsigned long long pv=P[i];
        int r=(int)(0xFFFFFFFFu-(unsigned int)pv);
        ipos[r]=(i<k)? i : -1;
        if(i<k){
            unsigned int u=(unsigned int)(pv>>32);
            unsigned int f=u ^ ((u&0x80000000u)? 0x80000000u : 0xFFFFFFFFu);
            float key=__uint_as_float(f);
            perm[i]=r; vals[i]=key;
            sk[i]=key;
        }
    }
    __syncthreads();
    for(int idx=t;idx<k*FH;idx+=1024){
        int i=idx/FH, c=idx%FH;
        unsigned long long pv=P[i];
        int r=(int)(0xFFFFFFFFu-(unsigned int)pv);
        h[idx]=x[(size_t)r*FH+c]*sk[i];
    }
}

// ---------------- SpGEMM level1 (CSR out, input HAS diag entries) ----------------
template<int NCOL>
__global__ void __launch_bounds__(256) k_spgemm_csr(
        const int* __restrict__ inIdx,const float* __restrict__ inVal,const int* __restrict__ inCnt,int inMaxd,
        const int* __restrict__ perm,const int* __restrict__ ipos,
        int* __restrict__ outIdx,float* __restrict__ outVal,int* __restrict__ outCnt,int outMaxd,
        float* __restrict__ dinv){
    __shared__ float acc[NCOL];
    int i=blockIdx.x, t=threadIdx.x;
    for(int j=t;j<NCOL;j+=256) acc[j]=0.f;
    __syncthreads();
    int r0=perm[i];
    int cr=inCnt[r0];
    const int* rip=inIdx+(size_t)r0*inMaxd;
    const float* rvp=inVal+(size_t)r0*inMaxd;
    int warp=t>>5, lane=t&31;
    for(int e=warp;e<cr;e+=8){
        int k=rip[e];
        float rv=rvp[e] + ((k==r0)?1.f:0.f);
        int ck=inCnt[k];
        const int* kip=inIdx+(size_t)k*inMaxd;
        const float* kvp=inVal+(size_t)k*inMaxd;
        for(int f=lane;f<ck;f+=32){
            int s=kip[f];
            float cv=kvp[f] + ((s==k)?1.f:0.f);
            int j=ipos[s];
            if(j>=0) atomicAdd(&acc[j], rv*cv);
        }
    }
    __syncthreads();
    if(t==0) acc[i]=0.f;
    __syncthreads();
    if(warp==0){
        int c=0; float rs=0.f;
        for(int base=0;base<NCOL;base+=32){
            int j=base+lane;
            float v=acc[j];
            bool p=(v!=0.f);
            unsigned m=__ballot_sync(0xffffffffu,p);
            if(p){
                int off=c+__popc(m&((1u<<lane)-1u));
                outIdx[(size_t)i*outMaxd+off]=j;
                outVal[(size_t)i*outMaxd+off]=v;
                rs+=v;
            }
            c+=__popc(m);
        }
        #pragma unroll
        for(int o=16;o;o>>=1) rs+=__shfl_xor_sync(0xffffffffu,rs,o);
        if(lane==0){ outCnt[i]=c; dinv[i]=rsqrtf(rs+2.f); }
    }
}

// ---------------- SpGEMM level2 (dense out, input CSR has NO diag) ----------------
template<int NCOL>
__global__ void __launch_bounds__(256) k_spgemm_dense(
        const int* __restrict__ inIdx,const float* __restrict__ inVal,const int* __restrict__ inCnt,int inMaxd,
        const int* __restrict__ perm,const int* __restrict__ ipos,
        float* __restrict__ outD,float* __restrict__ dinv){
    __shared__ float acc[NCOL];
    __shared__ float red[8];
    int i=blockIdx.x, t=threadIdx.x;
    for(int j=t;j<NCOL;j+=256) acc[j]=0.f;
    __syncthreads();
    int r0=perm[i];
    int cr=inCnt[r0];
    int total=cr+1;
    const int* rip=inIdx+(size_t)r0*inMaxd;
    const float* rvp=inVal+(size_t)r0*inMaxd;
    int warp=t>>5, lane=t&31;
    for(int e=warp;e<total;e+=8){
        int k; float rv;
        if(e<cr){ k=rip[e]; rv=rvp[e]; }
        else    { k=r0; rv=1.f; }
        int ck=inCnt[k];
        const int* kip=inIdx+(size_t)k*inMaxd;
        const float* kvp=inVal+(size_t)k*inMaxd;
        int tot2=ck+1;
        for(int f=lane;f<tot2;f+=32){
            int s; float cv;
            if(f<ck){ s=kip[f]; cv=kvp[f]; }
            else    { s=k; cv=1.f; }
            int j=ipos[s];
            if(j>=0) atomicAdd(&acc[j], rv*cv);
        }
    }
    __syncthreads();
    if(t==0) acc[i]=0.f;
    __syncthreads();
    float rs=0.f;
    for(int j=t;j<NCOL;j+=256){ rs+=acc[j]; outD[(size_t)i*NCOL+j]=acc[j]; }
    #pragma unroll
    for(int o=16;o;o>>=1) rs+=__shfl_xor_sync(0xffffffffu,rs,o);
    if(lane==0) red[warp]=rs;
    __syncthreads();
    if(t==0){
        float s=0.f;
        #pragma unroll
        for(int w=0;w<8;w++) s+=red[w];
        dinv[i]=rsqrtf(s+2.f);
    }
}

// ---------------- level-3 gathers ----------------
__global__ void k_gatherR(const float* __restrict__ A,int n,const int* __restrict__ perm,int m,float* __restrict__ R){
    size_t t=(size_t)blockIdx.x*blockDim.x+threadIdx.x;
    if(t>=(size_t)m*n) return;
    int i=(int)(t/n), k=(int)(t%n);
    int pi=perm[i];
    R[t]=A[(size_t)pi*n+k] + ((k==pi)?1.f:0.f);
}
__global__ void k_gatherC(const float* __restrict__ A,int n,const int* __restrict__ perm,int m,float* __restrict__ C){
    size_t t=(size_t)blockIdx.x*blockDim.x+threadIdx.x;
    if(t>=(size_t)m*n) return;
    int k=(int)(t/m), j=(int)(t%m);
    int pj=perm[j];
    C[t]=A[(size_t)k*n+pj] + ((k==pj)?1.f:0.f);
}

// ---------------- GAT ----------------
__global__ void k_esed(const float* __restrict__ feat,const float* __restrict__ asrc,const float* __restrict__ adst,int heads,float* __restrict__ es,float* __restrict__ ed){
    int w=(blockIdx.x*blockDim.x+threadIdx.x)>>5;
    int lane=threadIdx.x&31;
    if(w>=N0) return;
    for(int h=0;h<heads;h++){
        float a=0.f,d=0.f;
        for(int c=lane;c<FO;c+=32){
            float f=feat[(size_t)w*(heads*FO)+h*FO+c];
            a+=f*asrc[h*FO+c];
            d+=f*adst[h*FO+c];
        }
        #pragma unroll
        for(int o=16;o;o>>=1){ a+=__shfl_xor_sync(0xffffffffu,a,o); d+=__shfl_xor_sync(0xffffffffu,d,o); }
        if(lane==0){ es[w*heads+h]=a; ed[w*heads+h]=d; }
    }
}

template<int HEADS,int MODE>
__global__ void __launch_bounds__(128) k_gat(const float* __restrict__ feat,const float* __restrict__ es,const float* __restrict__ ed,
                                             const float* __restrict__ bias,const float* __restrict__ res,const float* __restrict__ resb,
                                             float* __restrict__ out){
    __shared__ int snbr[MAXD0];
    __shared__ float salpha[MAXD0*HEADS];
    __shared__ float smax[HEADS], sinv[HEADS];
    int d=blockIdx.x, t=threadIdx.x;
    int cnt=g_cnt0[d];
    for(int i=t;i<cnt;i+=128) snbr[i]=g_idx0[(size_t)d*MAXD0+i];
    __syncthreads();
    for(int i=t;i<cnt;i+=128){
        int s=snbr[i];
        #pragma unroll
        for(int h=0;h<HEADS;h++){
            float l=ed[d*HEADS+h]+es[s*HEADS+h];
            l = (l>0.f)? l : 0.2f*l;
            salpha[i*HEADS+h]=l;
        }
    }
    __syncthreads();
    if(t<HEADS){
        float mx=-1e30f;
        for(int i=0;i<cnt;i++) mx=fmaxf(mx,salpha[i*HEADS+t]);
        float sm=0.f;
        for(int i=0;i<cnt;i++) sm+=expf(salpha[i*HEADS+t]-mx);
        smax[t]=mx; sinv[t]=1.f/sm;
    }
    __syncthreads();
    for(int i=t;i<cnt*HEADS;i+=128){
        int h=i%HEADS;
        salpha[i]=expf(salpha[i]-smax[h])*sinv[h];
    }
    __syncthreads();
    #pragma unroll
    for(int h=0;h<HEADS;h++){
        float acc=0.f;
        for(int i=0;i<cnt;i++)
            acc += salpha[i*HEADS+h]*feat[(size_t)snbr[i]*(HEADS*FO)+h*FO+t];
        if(MODE==0){
            float v=acc+bias[h*FO+t];
            out[(size_t)d*(HEADS*FO)+h*FO+t]= (v>0.f)? v : expm1f(v);
        } else {
            out[(size_t)d*FO+t]=acc+bias[t]+res[(size_t)d*FO+t]+resb[t];
        }
    }
}

// ---------------- host ----------------
template<typename T> static T* symaddr(const void* sym){
    void* p=nullptr;
    cudaGetSymbolAddress(&p, sym);
    return (T*)p;
}

static void gBig(int M,int N,int K,int KS,const float*A,const float*B,float*dest){
    dim3 g(N/64, M/64, KS);
    gemmBig<<<g,256>>>(M,N,K,KS,A,B,dest);
}
static void g16(int M,int N,int K,const float*A,const float*B,float*C){
    dim3 g(N/64, M/16);
    gemm16<0,0><<<g,256>>>(M,N,K,A,B,C,nullptr,nullptr,nullptr);
}
static void g16_s(int M,int N,int K,const float*A,const float*B,float*C,const float*di){
    dim3 g(N/64, M/16);
    gemm16<3,0><<<g,256>>>(M,N,K,A,B,C,di,nullptr,nullptr);
}
static void g16_m(int M,int N,int K,const float*A,const float*B,float*C,const int*ipos,const float*xs){
    dim3 g(N/64, M/16);
    gemm16<0,1><<<g,256>>>(M,N,K,A,B,C,nullptr,ipos,xs);
}
static void g16_ms(int M,int N,int K,const float*A,const float*B,float*C,const float*di,const int*ipos,const float*xs){
    dim3 g(N/64, M/16);
    gemm16<3,1><<<g,256>>>(M,N,K,A,B,C,di,ipos,xs);
}

extern "C" void kernel_launch(void* const* d_in, const int* in_sizes, int n_in,
                              void* d_out, int out_size) {
    const float* x      =(const float*)d_in[0];
    const int*   ei     =(const int*  )d_in[1];
    const float* w0=(const float*)d_in[2],  *b0=(const float*)d_in[3];
    const float* w1=(const float*)d_in[4],  *b1=(const float*)d_in[5];
    const float* w2=(const float*)d_in[6],  *b2=(const float*)d_in[7];
    const float* w3=(const float*)d_in[8],  *b3=(const float*)d_in[9];
    const float* p1=(const float*)d_in[10], *p2=(const float*)d_in[11], *p3=(const float*)d_in[12];
    const float* uw0=(const float*)d_in[13],*ub0=(const float*)d_in[14];
    const float* uw1=(const float*)d_in[15],*ub1=(const float*)d_in[16];
    const float* uw2=(const float*)d_in[17],*ub2=(const float*)d_in[18];
    const float* lng=(const float*)d_in[19],*lnb=(const float*)d_in[20];
    const float* resw=(const float*)d_in[21],*resb=(const float*)d_in[22];
    const float* g1w=(const float*)d_in[23],*g1as=(const float*)d_in[24],*g1ad=(const float*)d_in[25],*g1b=(const float*)d_in[26];
    const float* g2w=(const float*)d_in[27],*g2as=(const float*)d_in[28],*g2ad=(const float*)d_in[29],*g2b=(const float*)d_in[30];

    unsigned char* A0b=symaddr<unsigned char>(g_A0b);
    int* idx0=symaddr<int>(g_idx0); float* val0=symaddr<float>(g_val0);
    float* val0s=symaddr<float>(g_val0s); int* cnt0=symaddr<int>(g_cnt0);
    int* idx1=symaddr<int>(g_idx1); float* val1=symaddr<float>(g_val1);
    float* val1s=symaddr<float>(g_val1s); int* cnt1=symaddr<int>(g_cnt1);
    float* A2d=symaddr<float>(g_A2d); float* A3d=symaddr<float>(g_A3d);
    float* Rg=symaddr<float>(g_Rg); float* Cg=symaddr<float>(g_Cg);
    float* part=symaddr<float>(g_part);
    float* Y=symaddr<float>(g_Y);   float* S=symaddr<float>(g_S);
    float* x0b=symaddr<float>(g_x0);float* x1b=symaddr<float>(g_x1);
    float* x2b=symaddr<float>(g_x2);float* x3b=symaddr<float>(g_x3);
    float* hb=symaddr<float>(g_hbuf); float* upb=symaddr<float>(g_up);
    float* Ub=symaddr<float>(g_U);  float* Rb=symaddr<float>(g_res);
    float* F1=symaddr<float>(g_feat1); float* GO=symaddr<float>(g_gout);
    float* di0=symaddr<float>(g_dinv0); float* df0=symaddr<float>(g_dfix0);
    float* di1=symaddr<float>(g_dinv1); float* di2=symaddr<float>(g_dinv2); float* di3=symaddr<float>(g_dinv3);
    int* pm1=symaddr<int>(g_perm1); float* vl1=symaddr<float>(g_vals1);
    int* pm2=symaddr<int>(g_perm2); float* vl2=symaddr<float>(g_vals2);
    int* pm3=symaddr<int>(g_perm3); float* vl3=symaddr<float>(g_vals3);
    int* ip1=symaddr<int>(g_ipos1); int* ip2=symaddr<int>(g_ipos2); int* ip3=symaddr<int>(g_ipos3);
    float* ES=symaddr<float>(g_es); float* ED=symaddr<float>(g_ed);
    float* out=(float*)d_out;

    // ---- build A0 (bytes) + CSR0 + prescale ----
    cudaMemsetAsync(A0b,0,(size_t)N0*N0,0);
    k_buildA0<<<cdiv(NE,256),256>>>(ei,(unsigned int*)A0b);
    k_csr0<<<cdiv(N0,8),256>>>(A0b,idx0,val0,cnt0,di0,df0);
    k_prescale_csr<<<cdiv(N0,8),256>>>(N0,idx0,val0,cnt0,MAXD0,di0,val0s);

    // ---- gcn0 down ----
    k_xw0<<<cdiv(N0*FH,256),256>>>(x,w0,Y);
    k_spmmf<64><<<cdiv(N0*64,256),256>>>(N0,idx0,val0s,cnt0,MAXD0,Y,di0,df0,b0,x0b,1);

    // ---- pool1 + A1 (sparse) ----
    k_pool<N0><<<1,1024>>>(x0b,p1,N1,pm1,vl1,ip1,hb);
    k_spgemm_csr<N1><<<N1,256>>>(idx0,val0,cnt0,MAXD0,pm1,ip1,idx1,val1,cnt1,MAXD1,di1);
    k_prescale_csr<<<cdiv(N1,8),256>>>(N1,idx1,val1,cnt1,MAXD1,di1,val1s);

    // ---- gcn1 down ----
    g16(N1,FH,FH,hb,w1,Y);
    k_spmmf<64><<<cdiv(N1*64,256),256>>>(N1,idx1,val1s,cnt1,MAXD1,Y,di1,nullptr,b1,x1b,1);

    // ---- pool2 + A2 (dense out) ----
    k_pool<N1><<<1,1024>>>(x1b,p2,N2,pm2,vl2,ip2,hb);
    k_spgemm_dense<N2><<<N2,256>>>(idx1,val1,cnt1,MAXD1,pm2,ip2,A2d,di2);

    // ---- gcn2 down (dense, lazy scale, split-K) ----
    g16_s(N2,FH,FH,hb,w2,Y,di2);
    gBig(N2,FH,N2,8,A2d,Y,part);
    k_kred_gcn<<<cdiv(N2*FH,256),256>>>(N2,FH,8,part,Y,di2,b2,x2b,1);

    // ---- pool3 + A3 (dense GEMM, split-K) ----
    k_pool<N2><<<1,1024>>>(x2b,p3,N3,pm3,vl3,ip3,hb);
    k_gatherR<<<cdiv(N3*N2,256),256>>>(A2d,N2,pm3,N3,Rg);
    k_gatherC<<<cdiv(N3*N2,256),256>>>(A2d,N2,pm3,N3,Cg);
    gBig(N3,N3,N2,4,Rg,Cg,part);
    k_finishA3red<<<N3,256>>>(part,A3d,di3);

    // ---- gcn3 down ----
    g16_s(N3,FH,FH,hb,w3,Y,di3);
    gBig(N3,FH,N3,8,A3d,Y,part);
    k_kred_gcn<<<cdiv(N3*FH,256),256>>>(N3,FH,8,part,Y,di3,b3,x3b,1);

    // ---- up path ----
    g16_ms(N2,FH,FH,x2b,uw0,Y,di2,ip3,x3b);
    gBig(N2,FH,N2,8,A2d,Y,part);
    k_kred_gcn<<<cdiv(N2*FH,256),256>>>(N2,FH,8,part,Y,di2,ub0,upb,1);

    g16_m(N1,FH,FH,x1b,uw1,Y,ip2,upb);
    k_spmmf<64><<<cdiv(N1*64,256),256>>>(N1,idx1,val1s,cnt1,MAXD1,Y,di1,nullptr,ub1,upb,1);

    g16_m(N0,FO,FH,x0b,uw2,Y,ip1,upb);
    k_spmmLN<<<N0/2,256>>>(idx0,val0s,cnt0,Y,di0,df0,ub2,lng,lnb,Ub);

    // ---- residual + GAT layers ----
    gBig(N0,FO,FO,1,Ub,resw,Rb);
    gBig(N0,4*FO,FO,1,Ub,g1w,F1);
    k_esed<<<cdiv(N0,8),256>>>(F1,g1as,g1ad,4,ES,ED);
    k_gat<4,0><<<N0,128>>>(F1,ES,ED,g1b,nullptr,nullptr,GO);

    gBig(N0,FO,4*FO,1,GO,g2w,S);
    k_esed<<<cdiv(N0,8),256>>>(S,g2as,g2ad,1,ES,ED);
    k_gat<1,1><<<N0,128>>>(S,ES,ED,g2b,Rb,resb,out);
}

// round 9
// speedup vs baseline: 4.7530x; 1.0150x over previous
#include <cuda_runtime.h>
#include <cuda_bf16.h>
#include <math.h>

// ---------------- problem constants ----------------
#define N0 4096
#define N1 2048
#define N2 1024
#define N3 512
#define NE 65536
#define FH 64
#define FO 128
#define MAXD0 128
#define MAXD1 2048

// ---------------- static device scratch ----------------
__device__ unsigned char g_A0b[(size_t)N0*N0];
__device__ int   g_idx0[(size_t)N0*MAXD0]; __device__ float g_val0[(size_t)N0*MAXD0]; __device__ int g_cnt0[N0];
__device__ int   g_idx1[(size_t)N1*MAXD1]; __device__ float g_val1[(size_t)N1*MAXD1]; __device__ int g_cnt1[N1];
__device__ float g_A2d[(size_t)N2*N2];
__device__ float g_A3d[(size_t)N3*N3];
__device__ float g_Rg[(size_t)N3*N2];
__device__ float g_Cg[(size_t)N2*N3];
__device__ float g_part[1<<20];
__device__ float g_Y[(size_t)N0*FO];
__device__ float g_S[(size_t)N0*FO];
__device__ float g_x0[N0*FH], g_x1[N1*FH], g_x2[N2*FH], g_x3[N3*FH];
__device__ float g_hbuf[N0*FH];
__device__ float g_up[N1*FH];
__device__ float g_U[N0*FO];
__device__ float g_res[N0*FO];
__device__ float g_feat1[(size_t)N0*512];
__device__ float g_gout[(size_t)N0*512];
__device__ float g_dinv0[N0], g_dfix0[N0];
__device__ float g_dinv1[N1], g_dinv2[N2], g_dinv3[N3];
__device__ int   g_perm1[N1]; __device__ float g_vals1[N1];
__device__ int   g_perm2[N2]; __device__ float g_vals2[N2];
__device__ int   g_perm3[N3]; __device__ float g_vals3[N3];
__device__ int   g_ipos1[N0], g_ipos2[N1], g_ipos3[N2];
__device__ float g_es[N0*4], g_ed[N0*4];

static inline int cdiv(int a,int b){return (a+b-1)/b;}

// ---------------- gemmBig: 64x64x16, TM=TN=4, optional split-K, optional B row-scale ----------------
template<int BSCALE>
__global__ void __launch_bounds__(256)
gemmBig(int M,int N,int K,int KS,const float* __restrict__ A,const float* __restrict__ B,
        float* __restrict__ dest,const float* __restrict__ bs){
    __shared__ __align__(16) float As[16][64];
    __shared__ __align__(16) float Bs[16][64];
    const int bm=blockIdx.y*64, bn=blockIdx.x*64, z=blockIdx.z;
    const int tid=threadIdx.x;
    const int trow=tid/16, tcol=tid%16;
    const int kchunk=K/KS;
    const int kbeg=z*kchunk, kend=kbeg+kchunk;
    float acc[4][4];
    #pragma unroll
    for(int i=0;i<4;i++)
        #pragma unroll
        for(int j=0;j<4;j++) acc[i][j]=0.f;

    for(int k0=kbeg;k0<kend;k0+=16){
        {
            int m=tid/4, kq=tid%4;
            float4 v=*(const float4*)(A+(size_t)(bm+m)*K+k0+kq*4);
            As[kq*4+0][m]=v.x; As[kq*4+1][m]=v.y; As[kq*4+2][m]=v.z; As[kq*4+3][m]=v.w;
        }
        {
            int k=tid/16, nq=tid%16;
            float4 v=*(const float4*)(B+(size_t)(k0+k)*N+bn+nq*4);
            if(BSCALE){
                float s=bs[k0+k];
                v.x*=s; v.y*=s; v.z*=s; v.w*=s;
            }
            *(float4*)&Bs[k][nq*4]=v;
        }
        __syncthreads();
        #pragma unroll
        for(int kk=0;kk<16;kk++){
            float4 ra=*(const float4*)&As[kk][trow*4];
            float4 rb=*(const float4*)&Bs[kk][tcol*4];
            float a[4]={ra.x,ra.y,ra.z,ra.w};
            float b[4]={rb.x,rb.y,rb.z,rb.w};
            #pragma unroll
            for(int i=0;i<4;i++)
                #pragma unroll
                for(int j=0;j<4;j++) acc[i][j]+=a[i]*b[j];
        }
        __syncthreads();
    }
    float* out=dest+(size_t)z*M*N;
    #pragma unroll
    for(int i=0;i<4;i++){
        int gm=bm+trow*4+i;
        #pragma unroll
        for(int j=0;j<4;j++){
            out[(size_t)gm*N+bn+tcol*4+j]=acc[i][j];
        }
    }
}

// split-K reduce + GCN epilogue (raw Y): v = di*acc + 2*di*di*Y + b
__global__ void k_kred_gcn(int n,int f,int KS,const float* __restrict__ part,
                           const float* __restrict__ Y,const float* __restrict__ di,
                           const float* __restrict__ b,float* __restrict__ out,int relu){
    int t=blockIdx.x*blockDim.x+threadIdx.x;
    if(t>=n*f) return;
    float acc=0.f;
    for(int z=0;z<KS;z++) acc+=part[(size_t)z*n*f+t];
    int r=t/f;
    float d=di[r];
    float v=d*acc + 2.f*d*d*Y[t] + b[t%f];
    out[t]= relu? fmaxf(v,0.f) : v;
}

// A3 split-K reduce (KS=4) + zero diag + rowsum -> dinv3
__global__ void __launch_bounds__(256) k_finishA3red(const float* __restrict__ part,
                                                     float* __restrict__ A3,float* __restrict__ dinv){
    __shared__ float red[8];
    int r=blockIdx.x, t=threadIdx.x;
    float s=0.f;
    for(int j=t;j<N3;j+=256){
        float acc=part[(size_t)0*N3*N3 + r*N3 + j]
                 +part[(size_t)1*N3*N3 + r*N3 + j]
                 +part[(size_t)2*N3*N3 + r*N3 + j]
                 +part[(size_t)3*N3*N3 + r*N3 + j];
        if(j==r) acc=0.f;
        A3[(size_t)r*N3+j]=acc;
        s+=acc;
    }
    #pragma unroll
    for(int o=16;o;o>>=1) s+=__shfl_xor_sync(0xffffffffu,s,o);
    if((t&31)==0) red[t>>5]=s;
    __syncthreads();
    if(t==0){
        float ss=0.f;
        #pragma unroll
        for(int w=0;w<8;w++) ss+=red[w];
        dinv[r]=rsqrtf(ss+2.f);
    }
}

// ---------------- gemm16: 16x64x16, TM=1,TN=4 ----------------
// MERGE: A element = Af[gm,gk] + (ipos[gm]>=0 ? xs[ipos[gm],gk] : 0)
template<int MERGE>
__global__ void __launch_bounds__(256)
gemm16(int M,int N,int K,const float* __restrict__ Af,const float* __restrict__ B,
       float* __restrict__ C,const int* __restrict__ ipos,const float* __restrict__ xs){
    __shared__ __align__(16) float As[16][16];
    __shared__ __align__(16) float Bs[16][64];
    const int bm=blockIdx.y*16, bn=blockIdx.x*64;
    const int tid=threadIdx.x;
    const int trow=tid/16, tcol=tid%16;
    float acc[4]={0.f,0.f,0.f,0.f};
    for(int k0=0;k0<K;k0+=16){
        {
            int m=tid/16, k=tid%16;
            int gm=bm+m, gk=k0+k;
            float a=Af[(size_t)gm*K+gk];
            if(MERGE){ int j=ipos[gm]; if(j>=0) a+=xs[(size_t)j*K+gk]; }
            As[k][m]=a;
        }
        {
            int k=tid/16, nq=tid%16;
            *(float4*)&Bs[k][nq*4] = *(const float4*)(B+(size_t)(k0+k)*N+bn+nq*4);
        }
        __syncthreads();
        #pragma unroll
        for(int kk=0;kk<16;kk++){
            float a=As[kk][trow];
            float4 rb=*(const float4*)&Bs[kk][tcol*4];
            acc[0]+=a*rb.x; acc[1]+=a*rb.y; acc[2]+=a*rb.z; acc[3]+=a*rb.w;
        }
        __syncthreads();
    }
    int gm=bm+trow;
    #pragma unroll
    for(int j=0;j<4;j++)
        C[(size_t)gm*N+bn+tcol*4+j]=acc[j];
}

// ---------------- graph build ----------------
__global__ void k_buildA0(const int* __restrict__ ei, unsigned int* __restrict__ Aw){
    int e = blockIdx.x*blockDim.x+threadIdx.x;
    if(e<NE){
        int s=ei[e];
        int d=ei[NE+e];
        size_t byteoff=(size_t)d*N0+s;
        atomicAdd(&Aw[byteoff>>2], 1u<<((s&3)*8));
    }
}

__global__ void k_csr0(const unsigned char* __restrict__ Ab,int* __restrict__ idx,float* __restrict__ val,
                       int* __restrict__ cnt,float* __restrict__ dinv,float* __restrict__ dfix){
    int w=(blockIdx.x*blockDim.x+threadIdx.x)>>5;
    int lane=threadIdx.x&31;
    if(w>=N0) return;
    const unsigned int* row=(const unsigned int*)(Ab+(size_t)w*N0);
    int c=0; float rs=0.f;
    for(int base=0;base<N0/4;base+=32){
        unsigned int wv=row[base+lane];
        int colbase=(base+lane)*4;
        #pragma unroll
        for(int b=0;b<4;b++){
            int v=(wv>>(8*b))&255;
            int col=colbase+b;
            bool p=(v!=0)||(col==w);
            unsigned m=__ballot_sync(0xffffffffu,p);
            if(p){
                int off=c+__popc(m&((1u<<lane)-1u));
                idx[(size_t)w*MAXD0+off]=col;
                val[(size_t)w*MAXD0+off]=(float)v;
                rs+=(float)v;
            }
            c+=__popc(m);
        }
    }
    #pragma unroll
    for(int o=16;o;o>>=1) rs+=__shfl_xor_sync(0xffffffffu,rs,o);
    if(lane==0){
        float d=(float)Ab[(size_t)w*N0+w];
        float fx=(d==0.f)?2.f:0.f;
        cnt[w]=c;
        dfix[w]=fx;
        dinv[w]=rsqrtf(rs+fx);
    }
}

// ---------------- level0 fused SpMM: computes x@w0 per neighbor on the fly ----------------
__global__ void __launch_bounds__(256) k_spmm0(const int* __restrict__ idx,const float* __restrict__ val,
                        const int* __restrict__ cnt,const float* __restrict__ dinv,
                        const float* __restrict__ dfix,
                        const float* __restrict__ x,const float* __restrict__ w,
                        const float* __restrict__ b,float* __restrict__ out){
    __shared__ float sw[3*FH];
    if(threadIdx.x<3*FH) sw[threadIdx.x]=w[threadIdx.x];
    __syncthreads();
    int r = blockIdx.x*4 + threadIdx.x/FH;
    int c = threadIdx.x%FH;
    int cn=cnt[r];
    const int* ip=idx+(size_t)r*MAXD0;
    const float* vp=val+(size_t)r*MAXD0;
    float w0c=sw[c], w1c=sw[FH+c], w2c=sw[2*FH+c];
    float acc=0.f;
    for(int e=0;e<cn;e++){
        int s=ip[e];
        const float* xr=x+(size_t)s*3;
        float ys=dinv[s]*(xr[0]*w0c+xr[1]*w1c+xr[2]*w2c);
        acc += vp[e]*ys;
    }
    float di=dinv[r];
    const float* xr=x+(size_t)r*3;
    float ysS=di*(xr[0]*w0c+xr[1]*w1c+xr[2]*w2c);
    float v = di*acc + dfix[r]*di*ysS + b[c];
    out[(size_t)r*FH+c]=fmaxf(v,0.f);
}

// ---------------- CSR SpMM with inline di gather + GCN epilogue ----------------
template<int F>
__global__ void k_spmmf(int n,const int* __restrict__ idx,const float* __restrict__ val,
                        const int* __restrict__ cnt,int maxd,
                        const float* __restrict__ Y,const float* __restrict__ dinv,
                        const float* __restrict__ dfix,const float* __restrict__ b,
                        float* __restrict__ out,int relu){
    int r = blockIdx.x*(256/F) + threadIdx.x/F;
    int c = threadIdx.x%F;
    if(r>=n) return;
    int cn=cnt[r];
    const int* ip=idx+(size_t)r*maxd;
    const float* vp=val+(size_t)r*maxd;
    float acc=0.f;
    for(int e=0;e<cn;e++){
        int s=ip[e];
        acc += vp[e]*dinv[s]*Y[(size_t)s*F+c];
    }
    float fx = dfix? dfix[r] : 2.0f;
    float di = dinv[r];
    float v = di*acc + fx*di*di*Y[(size_t)r*F+c] + b[c];
    out[(size_t)r*F+c] = relu? fmaxf(v,0.f) : v;
}

// CSR SpMM (F=128, raw vals + di gather) + LayerNorm fused
__global__ void __launch_bounds__(256) k_spmmLN(const int* __restrict__ idx,const float* __restrict__ val,
                        const int* __restrict__ cnt,
                        const float* __restrict__ Y,const float* __restrict__ dinv,
                        const float* __restrict__ dfix,const float* __restrict__ b,
                        const float* __restrict__ lg,const float* __restrict__ lb,
                        float* __restrict__ u){
    __shared__ float sh[256];
    int r = blockIdx.x*2 + threadIdx.x/128;
    int c = threadIdx.x%128;
    int base = threadIdx.x & 128;
    int cn=cnt[r];
    const int* ip=idx+(size_t)r*MAXD0;
    const float* vp=val+(size_t)r*MAXD0;
    float acc=0.f;
    for(int e=0;e<cn;e++){
        int s=ip[e];
        acc += vp[e]*dinv[s]*Y[(size_t)s*FO+c];
    }
    float di=dinv[r];
    float v = di*acc + dfix[r]*di*di*Y[(size_t)r*FO+c] + b[c];
    sh[threadIdx.x]=v; __syncthreads();
    for(int o=64;o;o>>=1){ if(c<o) sh[base+c]+=sh[base+c+o]; __syncthreads(); }
    float mu=sh[base]/128.f; __syncthreads();
    float d=v-mu;
    sh[threadIdx.x]=d*d; __syncthreads();
    for(int o=64;o;o>>=1){ if(c<o) sh[base+c]+=sh[base+c+o]; __syncthreads(); }
    float var=sh[base]/128.f;
    u[(size_t)r*FO+c]=d*rsqrtf(var+1e-6f)*lg[c]+lb[c];
}

// ---------------- fused pool ----------------
template<int N>
__global__ void __launch_bounds__(1024) k_pool(const float* __restrict__ x,const float* __restrict__ p,
                                               int k,int* __restrict__ perm,float* __restrict__ vals,
                                               int* __restrict__ ipos,float* __restrict__ h){
    __shared__ unsigned long long P[N];
    __shared__ float sk[2048];
    int t=threadIdx.x;
    float pn=0.f;
    #pragma unroll
    for(int c=0;c<FH;c++){ float pv=p[c]; pn+=pv*pv; }
    float rn=rsqrtf(pn);
    for(int r=t;r<N;r+=1024){
        float d=0.f;
        #pragma unroll
        for(int c=0;c<FH;c++) d+=x[(size_t)r*FH+c]*p[c];
        float key=tanhf(d*rn);
        unsigned int f=__float_as_uint(key);
        unsigned int u=f ^ ((f&0x80000000u)? 0xFFFFFFFFu : 0x80000000u);
        P[r]=((unsigned long long)u<<32) | (unsigned int)(0xFFFFFFFFu - r);
    }
    __syncthreads();
    for(int size=2;size<=N;size<<=1){
        for(int stride=size>>1;stride>0;stride>>=1){
            for(int i=t;i<(N>>1);i+=1024){
                int lo = 2*i - (i&(stride-1));
                int hi = lo+stride;
                bool up = ((lo & size)==0);
                unsigned long long a=P[lo], b=P[hi];
                bool sw = up ? (b>a) : (a>b);
                if(sw){ P[lo]=b; P[hi]=a; }
            }
            __syncthreads();
        }
    }
    for(int i=t;i<N;i+=1024){
        unsigned long long pv=P[i];
        int r=(int)(0xFFFFFFFFu-(unsigned int)pv);
        ipos[r]=(i<k)? i : -1;
        if(i<k){
            unsigned int u=(unsigned int)(pv>>32);
            unsigned int f=u ^ ((u&0x80000000u)? 0x80000000u : 0xFFFFFFFFu);
            float key=__uint_as_float(f);
            perm[i]=r; vals[i]=key;
            sk[i]=key;
        }
    }
    __syncthreads();
    for(int idx=t;idx<k*FH;idx+=1024){
        int i=idx/FH, c=idx%FH;
        unsigned long long pv=P[i];
        int r=(int)(0xFFFFFFFFu-(unsigned int)pv);
        h[idx]=x[(size_t)r*FH+c]*sk[i];
    }
}

// ---------------- SpGEMM level1 (CSR out, input HAS diag entries) ----------------
template<int NCOL>
__global__ void __launch_bounds__(256) k_spgemm_csr(
        const int* __restrict__ inIdx,const float* __restrict__ inVal,const int* __restrict__ inCnt,int inMaxd,
        const int* __restrict__ perm,const int* __restrict__ ipos,
        int* __restrict__ outIdx,float* __restrict__ outVal,int* __restrict__ outCnt,int outMaxd,
        float* __restrict__ dinv){
    __shared__ float acc[NCOL];
    int i=blockIdx.x, t=threadIdx.x;
    for(int j=t;j<NCOL;j+=256) acc[j]=0.f;
    __syncthreads();
    int r0=perm[i];
    int cr=inCnt[r0];
    const int* rip=inIdx+(size_t)r0*inMaxd;
    const float* rvp=inVal+(size_t)r0*inMaxd;
    int warp=t>>5, lane=t&31;
    for(int e=warp;e<cr;e+=8){
        int k=rip[e];
        float rv=rvp[e] + ((k==r0)?1.f:0.f);
        int ck=inCnt[k];
        const int* kip=inIdx+(size_t)k*inMaxd;
        const float* kvp=inVal+(size_t)k*inMaxd;
        for(int f=lane;f<ck;f+=32){
            int s=kip[f];
            float cv=kvp[f] + ((s==k)?1.f:0.f);
            int j=ipos[s];
            if(j>=0) atomicAdd(&acc[j], rv*cv);
        }
    }
    __syncthreads();
    if(t==0) acc[i]=0.f;
    __syncthreads();
    if(warp==0){
        int c=0; float rs=0.f;
        for(int base=0;base<NCOL;base+=32){
            int j=base+lane;
            float v=acc[j];
            bool p=(v!=0.f);
            unsigned m=__ballot_sync(0xffffffffu,p);
            if(p){
                int off=c+__popc(m&((1u<<lane)-1u));
                outIdx[(size_t)i*outMaxd+off]=j;
                outVal[(size_t)i*outMaxd+off]=v;
                rs+=v;
            }
            c+=__popc(m);
        }
        #pragma unroll
        for(int o=16;o;o>>=1) rs+=__shfl_xor_sync(0xffffffffu,rs,o);
        if(lane==0){ outCnt[i]=c; dinv[i]=rsqrtf(rs+2.f); }
    }
}

// ---------------- SpGEMM level2 (dense out, input CSR has NO diag) ----------------
template<int NCOL>
__global__ void __launch_bounds__(256) k_spgemm_dense(
        const int* __restrict__ inIdx,const float* __restrict__ inVal,const int* __restrict__ inCnt,int inMaxd,
        const int* __restrict__ perm,const int* __restrict__ ipos,
        float* __restrict__ outD,float* __restrict__ dinv){
    __shared__ float acc[NCOL];
    __shared__ float red[8];
    int i=blockIdx.x, t=threadIdx.x;
    for(int j=t;j<NCOL;j+=256) acc[j]=0.f;
    __syncthreads();
    int r0=perm[i];
    int cr=inCnt[r0];
    int total=cr+1;
    const int* rip=inIdx+(size_t)r0*inMaxd;
    const float* rvp=inVal+(size_t)r0*inMaxd;
    int warp=t>>5, lane=t&31;
    for(int e=warp;e<total;e+=8){
        int k; float rv;
        if(e<cr){ k=rip[e]; rv=rvp[e]; }
        else    { k=r0; rv=1.f; }
        int ck=inCnt[k];
        const int* kip=inIdx+(size_t)k*inMaxd;
        const float* kvp=inVal+(size_t)k*inMaxd;
        int tot2=ck+1;
        for(int f=lane;f<tot2;f+=32){
            int s; float cv;
            if(f<ck){ s=kip[f]; cv=kvp[f]; }
            else    { s=k; cv=1.f; }
            int j=ipos[s];
            if(j>=0) atomicAdd(&acc[j], rv*cv);
        }
    }
    __syncthreads();
    if(t==0) acc[i]=0.f;
    __syncthreads();
    float rs=0.f;
    for(int j=t;j<NCOL;j+=256){ rs+=acc[j]; outD[(size_t)i*NCOL+j]=acc[j]; }
    #pragma unroll
    for(int o=16;o;o>>=1) rs+=__shfl_xor_sync(0xffffffffu,rs,o);
    if(lane==0) red[warp]=rs;
    __syncthreads();
    if(t==0){
        float s=0.f;
        #pragma unroll
        for(int w=0;w<8;w++) s+=red[w];
        dinv[i]=rsqrtf(s+2.f);
    }
}

// ---------------- level-3 gathers ----------------
__global__ void k_gatherR(const float* __restrict__ A,int n,const int* __restrict__ perm,int m,float* __restrict__ R){
    size_t t=(size_t)blockIdx.x*blockDim.x+threadIdx.x;
    if(t>=(size_t)m*n) return;
    int i=(int)(t/n), k=(int)(t%n);
    int pi=perm[i];
    R[t]=A[(size_t)pi*n+k] + ((k==pi)?1.f:0.f);
}
__global__ void k_gatherC(const float* __restrict__ A,int n,const int* __restrict__ perm,int m,float* __restrict__ C){
    size_t t=(size_t)blockIdx.x*blockDim.x+threadIdx.x;
    if(t>=(size_t)m*n) return;
    int k=(int)(t/m), j=(int)(t%m);
    int pj=perm[j];
    C[t]=A[(size_t)k*n+pj] + ((k==pj)?1.f:0.f);
}

// ---------------- GAT ----------------
__global__ void k_esed(const float* __restrict__ feat,const float* __restrict__ asrc,const float* __restrict__ adst,int heads,float* __restrict__ es,float* __restrict__ ed){
    int w=(blockIdx.x*blockDim.x+threadIdx.x)>>5;
    int lane=threadIdx.x&31;
    if(w>=N0) return;
    for(int h=0;h<heads;h++){
        float a=0.f,d=0.f;
        for(int c=lane;c<FO;c+=32){
            float f=feat[(size_t)w*(heads*FO)+h*FO+c];
            a+=f*asrc[h*FO+c];
            d+=f*adst[h*FO+c];
        }
        #pragma unroll
        for(int o=16;o;o>>=1){ a+=__shfl_xor_sync(0xffffffffu,a,o); d+=__shfl_xor_sync(0xffffffffu,d,o); }
        if(lane==0){ es[w*heads+h]=a; ed[w*heads+h]=d; }
    }
}

template<int HEADS,int MODE>
__global__ void __launch_bounds__(128) k_gat(const float* __restrict__ feat,const float* __restrict__ es,const float* __restrict__ ed,
                                             const float* __restrict__ bias,const float* __restrict__ res,const float* __restrict__ resb,
                                             float* __restrict__ out){
    __shared__ int snbr[MAXD0];
    __shared__ float salpha[MAXD0*HEADS];
    __shared__ float smax[HEADS], sinv[HEADS];
    int d=blockIdx.x, t=threadIdx.x;
    int cnt=g_cnt0[d];
    for(int i=t;i<cnt;i+=128) snbr[i]=g_idx0[(size_t)d*MAXD0+i];
    __syncthreads();
    for(int i=t;i<cnt;i+=128){
        int s=snbr[i];
        #pragma unroll
        for(int h=0;h<HEADS;h++){
            float l=ed[d*HEADS+h]+es[s*HEADS+h];
            l = (l>0.f)? l : 0.2f*l;
            salpha[i*HEADS+h]=l;
        }
    }
    __syncthreads();
    if(t<HEADS){
        float mx=-1e30f;
        for(int i=0;i<cnt;i++) mx=fmaxf(mx,salpha[i*HEADS+t]);
        float sm=0.f;
        for(int i=0;i<cnt;i++) sm+=expf(salpha[i*HEADS+t]-mx);
        smax[t]=mx; sinv[t]=1.f/sm;
    }
    __syncthreads();
    for(int i=t;i<cnt*HEADS;i+=128){
        int h=i%HEADS;
        salpha[i]=expf(salpha[i]-smax[h])*sinv[h];
    }
    __syncthreads();
    #pragma unroll
    for(int h=0;h<HEADS;h++){
        float acc=0.f;
        for(int i=0;i<cnt;i++)
            acc += salpha[i*HEADS+h]*feat[(size_t)snbr[i]*(HEADS*FO)+h*FO+t];
        if(MODE==0){
            float v=acc+bias[h*FO+t];
            out[(size_t)d*(HEADS*FO)+h*FO+t]= (v>0.f)? v : expm1f(v);
        } else {
            out[(size_t)d*FO+t]=acc+bias[t]+res[(size_t)d*FO+t]+resb[t];
        }
    }
}

// ---------------- host ----------------
template<typename T> static T* symaddr(const void* sym){
    void* p=nullptr;
    cudaGetSymbolAddress(&p, sym);
    return (T*)p;
}

static void gBig(int M,int N,int K,int KS,const float*A,const float*B,float*dest,
                 const float*bs,cudaStream_t st){
    dim3 g(N/64, M/64, KS);
    if(bs) gemmBig<1><<<g,256,0,st>>>(M,N,K,KS,A,B,dest,bs);
    else   gemmBig<0><<<g,256,0,st>>>(M,N,K,KS,A,B,dest,nullptr);
}
static void g16(int M,int N,int K,const float*A,const float*B,float*C,cudaStream_t st){
    dim3 g(N/64, M/16);
    gemm16<0><<<g,256,0,st>>>(M,N,K,A,B,C,nullptr,nullptr);
}
static void g16_m(int M,int N,int K,const float*A,const float*B,float*C,const int*ipos,const float*xs){
    dim3 g(N/64, M/16);
    gemm16<1><<<g,256>>>(M,N,K,A,B,C,ipos,xs);
}

extern "C" void kernel_launch(void* const* d_in, const int* in_sizes, int n_in,
                              void* d_out, int out_size) {
    const float* x      =(const float*)d_in[0];
    const int*   ei     =(const int*  )d_in[1];
    const float* w0=(const float*)d_in[2],  *b0=(const float*)d_in[3];
    const float* w1=(const float*)d_in[4],  *b1=(const float*)d_in[5];
    const float* w2=(const float*)d_in[6],  *b2=(const float*)d_in[7];
    const float* w3=(const float*)d_in[8],  *b3=(const float*)d_in[9];
    const float* p1=(const float*)d_in[10], *p2=(const float*)d_in[11], *p3=(const float*)d_in[12];
    const float* uw0=(const float*)d_in[13],*ub0=(const float*)d_in[14];
    const float* uw1=(const float*)d_in[15],*ub1=(const float*)d_in[16];
    const float* uw2=(const float*)d_in[17],*ub2=(const float*)d_in[18];
    const float* lng=(const float*)d_in[19],*lnb=(const float*)d_in[20];
    const float* resw=(const float*)d_in[21],*resb=(const float*)d_in[22];
    const float* g1w=(const float*)d_in[23],*g1as=(const float*)d_in[24],*g1ad=(const float*)d_in[25],*g1b=(const float*)d_in[26];
    const float* g2w=(const float*)d_in[27],*g2as=(const float*)d_in[28],*g2ad=(const float*)d_in[29],*g2b=(const float*)d_in[30];

    unsigned char* A0b=symaddr<unsigned char>(g_A0b);
    int* idx0=symaddr<int>(g_idx0); float* val0=symaddr<float>(g_val0); int* cnt0=symaddr<int>(g_cnt0);
    int* idx1=symaddr<int>(g_idx1); float* val1=symaddr<float>(g_val1); int* cnt1=symaddr<int>(g_cnt1);
    float* A2d=symaddr<float>(g_A2d); float* A3d=symaddr<float>(g_A3d);
    float* Rg=symaddr<float>(g_Rg); float* Cg=symaddr<float>(g_Cg);
    float* part=symaddr<float>(g_part);
    float* Y=symaddr<float>(g_Y);   float* S=symaddr<float>(g_S);
    float* x0b=symaddr<float>(g_x0);float* x1b=symaddr<float>(g_x1);
    float* x2b=symaddr<float>(g_x2);float* x3b=symaddr<float>(g_x3);
    float* hb=symaddr<float>(g_hbuf); float* upb=symaddr<float>(g_up);
    float* Ub=symaddr<float>(g_U);  float* Rb=symaddr<float>(g_res);
    float* F1=symaddr<float>(g_feat1); float* GO=symaddr<float>(g_gout);
    float* di0=symaddr<float>(g_dinv0); float* df0=symaddr<float>(g_dfix0);
    float* di1=symaddr<float>(g_dinv1); float* di2=symaddr<float>(g_dinv2); float* di3=symaddr<float>(g_dinv3);
    int* pm1=symaddr<int>(g_perm1); float* vl1=symaddr<float>(g_vals1);
    int* pm2=symaddr<int>(g_perm2); float* vl2=symaddr<float>(g_vals2);
    int* pm3=symaddr<int>(g_perm3); float* vl3=symaddr<float>(g_vals3);
    int* ip1=symaddr<int>(g_ipos1); int* ip2=symaddr<int>(g_ipos2); int* ip3=symaddr<int>(g_ipos3);
    float* ES=symaddr<float>(g_es); float* ED=symaddr<float>(g_ed);
    float* out=(float*)d_out;

    // side stream + events (created once; host-side objects, not device memory)
    static cudaStream_t s2=nullptr;
    static cudaEvent_t ev[8];
    if(!s2){
        cudaStreamCreateWithFlags(&s2,cudaStreamNonBlocking);
        for(int i=0;i<8;i++) cudaEventCreateWithFlags(&ev[i],cudaEventDisableTiming);
    }
    auto FORK=[&](int i){ cudaEventRecord(ev[i],0); cudaStreamWaitEvent(s2,ev[i],0); };
    auto JOIN=[&](int i){ cudaEventRecord(ev[4+i],s2); cudaStreamWaitEvent(0,ev[4+i],0); };

    // ---- build A0 (bytes) + CSR0 ----
    cudaMemsetAsync(A0b,0,(size_t)N0*N0,0);
    k_buildA0<<<cdiv(NE,256),256>>>(ei,(unsigned int*)A0b);
    k_csr0<<<cdiv(N0,8),256>>>(A0b,idx0,val0,cnt0,di0,df0);

    // ---- gcn0 down (x@w0 fused into SpMM) ----
    k_spmm0<<<N0/4,256>>>(idx0,val0,cnt0,di0,df0,x,w0,b0,x0b);

    // ---- pool1 ; [SpGEMM1 || feature GEMM1] ----
    k_pool<N0><<<1,1024>>>(x0b,p1,N1,pm1,vl1,ip1,hb);
    FORK(0);
    k_spgemm_csr<N1><<<N1,256,0,s2>>>(idx0,val0,cnt0,MAXD0,pm1,ip1,idx1,val1,cnt1,MAXD1,di1);
    g16(N1,FH,FH,hb,w1,Y,0);
    JOIN(0);
    k_spmmf<64><<<cdiv(N1*64,256),256>>>(N1,idx1,val1,cnt1,MAXD1,Y,di1,nullptr,b1,x1b,1);

    // ---- pool2 ; [SpGEMM2(dense) || feature GEMM2] ----
    k_pool<N1><<<1,1024>>>(x1b,p2,N2,pm2,vl2,ip2,hb);
    FORK(1);
    k_spgemm_dense<N2><<<N2,256,0,s2>>>(idx1,val1,cnt1,MAXD1,pm2,ip2,A2d,di2);
    g16(N2,FH,FH,hb,w2,Y,0);
    JOIN(1);
    gBig(N2,FH,N2,8,A2d,Y,part,di2,0);
    k_kred_gcn<<<cdiv(N2*FH,256),256>>>(N2,FH,8,part,Y,di2,b2,x2b,1);

    // ---- pool3 ; [A3 construction || feature GEMM3] ----
    k_pool<N2><<<1,1024>>>(x2b,p3,N3,pm3,vl3,ip3,hb);
    FORK(2);
    k_gatherR<<<cdiv(N3*N2,256),256,0,s2>>>(A2d,N2,pm3,N3,Rg);
    k_gatherC<<<cdiv(N3*N2,256),256,0,s2>>>(A2d,N2,pm3,N3,Cg);
    gBig(N3,N3,N2,4,Rg,Cg,part,nullptr,s2);
    k_finishA3red<<<N3,256,0,s2>>>(part,A3d,di3);
    g16(N3,FH,FH,hb,w3,Y,0);
    JOIN(2);
    gBig(N3,FH,N3,8,A3d,Y,part,di3,0);
    k_kred_gcn<<<cdiv(N3*FH,256),256>>>(N3,FH,8,part,Y,di3,b3,x3b,1);

    // ---- up path ----
    g16_m(N2,FH,FH,x2b,uw0,Y,ip3,x3b);
    gBig(N2,FH,N2,8,A2d,Y,part,di2,0);
    k_kred_gcn<<<cdiv(N2*FH,256),256>>>(N2,FH,8,part,Y,di2,ub0,upb,1);

    g16_m(N1,FH,FH,x1b,uw1,Y,ip2,upb);
    k_spmmf<64><<<cdiv(N1*64,256),256>>>(N1,idx1,val1,cnt1,MAXD1,Y,di1,nullptr,ub1,upb,1);

    g16_m(N0,FO,FH,x0b,uw2,Y,ip1,upb);
    k_spmmLN<<<N0/2,256>>>(idx0,val0,cnt0,Y,di0,df0,ub2,lng,lnb,Ub);

    // ---- [residual GEMM || GAT1 chain] ----
    FORK(3);
    gBig(N0,FO,FO,1,Ub,resw,Rb,nullptr,s2);
    gBig(N0,4*FO,FO,1,Ub,g1w,F1,nullptr,0);
    k_esed<<<cdiv(N0,8),256>>>(F1,g1as,g1ad,4,ES,ED);
    k_gat<4,0><<<N0,128>>>(F1,ES,ED,g1b,nullptr,nullptr,GO);
    gBig(N0,FO,4*FO,1,GO,g2w,S,nullptr,0);
    k_esed<<<cdiv(N0,8),256>>>(S,g2as,g2ad,1,ES,ED);
    JOIN(3);
    k_gat<1,1><<<N0,128>>>(S,ES,ED,g2b,Rb,resb,out);
}